// round 13
// baseline (speedup 1.0000x reference)
#include <cuda_runtime.h>
#include <cuda_fp16.h>

#define N_USER 100000
#define N_ITEM 200000
#define N_NODE 300000
#define LATDIM 64
#define E_INTER 4000000
#define E_SOC   2000000

// fp32 dense scratch (inter keeps USER rows only)
__device__ __align__(256) float g_soc   [4][(size_t)N_USER * LATDIM];
__device__ __align__(256) float g_interU[4][(size_t)N_USER * LATDIM];
__device__ __align__(256) float g_fusedU[5][(size_t)N_USER * LATDIM];

// fp16 gather sources / shadows
// comb[k] = [ fp16(gate_k user rows) ; fp16(inter_{k} item rows) ]
__device__ __align__(256) __half g_comb[4][(size_t)N_NODE * LATDIM];
__device__ __align__(256) __half g_soch[3][(size_t)N_USER * LATDIM];
__device__ __align__(256) __half g_it3 [(size_t)N_ITEM * LATDIM];   // item rows of inter spmm 3

// CSR scratch. cnt arrays self-reset (zeroed by scan_final after use).
// cv[i] = (col, half2(v,v) bits)
__device__ int  g_icnt[N_NODE];
__device__ int  g_icur[N_NODE];
__device__ int  g_iptr[N_NODE + 1];
__device__ __align__(16) int2 g_icv[E_INTER];
__device__ int  g_ibsum[256];

__device__ int  g_scnt[N_USER];
__device__ int  g_scur[N_USER];
__device__ int  g_sptr[N_USER + 1];
__device__ __align__(16) int2 g_scv[E_SOC];
__device__ int  g_sbsum[256];

// ---------------------------------------------------------------------------
// CSR build
// ---------------------------------------------------------------------------
__global__ void hist_rows(const int* __restrict__ rows, int E, int* __restrict__ cnt)
{
    int i = blockIdx.x * blockDim.x + threadIdx.x;
    if (i < E) atomicAdd(&cnt[rows[i]], 1);
}

__global__ void block_sum(const int* __restrict__ cnt, int N, int* __restrict__ bsum)
{
    __shared__ int sh[256];
    int base = blockIdx.x * 2048;
    int s = 0;
    for (int i = threadIdx.x; i < 2048; i += 256) {
        int idx = base + i;
        s += (idx < N) ? cnt[idx] : 0;
    }
    sh[threadIdx.x] = s;
    __syncthreads();
    for (int o = 128; o; o >>= 1) {
        if (threadIdx.x < o) sh[threadIdx.x] += sh[threadIdx.x + o];
        __syncthreads();
    }
    if (threadIdx.x == 0) bsum[blockIdx.x] = sh[0];
}

__global__ void scan_final(int* __restrict__ cnt, int N,
                           const int* __restrict__ bsum, int NB,
                           int* __restrict__ ptr, int* __restrict__ cur, int E)
{
    __shared__ int shb[256];
    __shared__ int sh[256];
    int t = threadIdx.x;

    shb[t] = (t < NB) ? bsum[t] : 0;
    __syncthreads();
    for (int o = 1; o < 256; o <<= 1) {
        int y = (t >= o) ? shb[t - o] : 0;
        __syncthreads();
        shb[t] += y;
        __syncthreads();
    }
    int block_off = (blockIdx.x == 0) ? 0 : shb[blockIdx.x - 1];

    int base = blockIdx.x * 2048 + t * 8;
    int loc[8];
    int s = 0;
    #pragma unroll
    for (int j = 0; j < 8; j++) {
        int idx = base + j;
        loc[j] = (idx < N) ? cnt[idx] : 0;
        if (idx < N) cnt[idx] = 0;           // self-reset for next call
        s += loc[j];
    }
    sh[t] = s;
    __syncthreads();
    for (int o = 1; o < 256; o <<= 1) {
        int y = (t >= o) ? sh[t - o] : 0;
        __syncthreads();
        sh[t] += y;
        __syncthreads();
    }
    int run = block_off + sh[t] - s;
    #pragma unroll
    for (int j = 0; j < 8; j++) {
        int idx = base + j;
        if (idx < N) { ptr[idx] = run; cur[idx] = run; run += loc[j]; }
    }
    if (blockIdx.x == 0 && t == 0) ptr[N] = E;
}

__device__ __forceinline__ int pack_vv(float v)
{
    __half2 h = __floats2half2_rn(v, v);
    return *reinterpret_cast<int*>(&h);
}

__global__ void scatter_edges(const int* __restrict__ rows, const int* __restrict__ cols,
                              const float* __restrict__ vals, int E,
                              int* __restrict__ cur, int2* __restrict__ cv)
{
    int i = blockIdx.x * blockDim.x + threadIdx.x;
    if (i >= E) return;
    int p = atomicAdd(&cur[rows[i]], 1);
    cv[p] = make_int2(cols[i], pack_vv(vals[i]));
}

__global__ void scatter_conv(const int* __restrict__ rows, const int* __restrict__ cols,
                             const float* __restrict__ vals, int E,
                             int* __restrict__ cur, int2* __restrict__ cv,
                             const float2* __restrict__ iE2, __half2* __restrict__ dst2,
                             int nI2)
{
    int i = blockIdx.x * blockDim.x + threadIdx.x;
    if (i < E) {
        int p = atomicAdd(&cur[rows[i]], 1);
        cv[p] = make_int2(cols[i], pack_vv(vals[i]));
    }
    if (i < nI2) dst2[i] = __float22half2_rn(iE2[i]);
}

// ---------------------------------------------------------------------------
// CSR SpMM: 16 lanes/row, pair-lane split; row range [r0, r1).
//   Inner loop: per-lane fp16 HFMA2 accumulation over 4 edges, flushed to the
//   fp32 accumulator once per 8-edge iteration. Edge value pre-packed half2.
// ---------------------------------------------------------------------------
__device__ __forceinline__ __half2 as_h2(int bits)
{
    return *reinterpret_cast<__half2*>(&bits);
}

__device__ __forceinline__ void hacc4(__half2* h, uint4 w, __half2 v)
{
    h[0] = __hfma2(*reinterpret_cast<__half2*>(&w.x), v, h[0]);
    h[1] = __hfma2(*reinterpret_cast<__half2*>(&w.y), v, h[1]);
    h[2] = __hfma2(*reinterpret_cast<__half2*>(&w.z), v, h[2]);
    h[3] = __hfma2(*reinterpret_cast<__half2*>(&w.w), v, h[3]);
}

// exact fp32 path for tails
__device__ __forceinline__ void acc8f(float* acc, uint4 w, float v)
{
    float2 f0 = __half22float2(*reinterpret_cast<__half2*>(&w.x));
    float2 f1 = __half22float2(*reinterpret_cast<__half2*>(&w.y));
    float2 f2 = __half22float2(*reinterpret_cast<__half2*>(&w.z));
    float2 f3 = __half22float2(*reinterpret_cast<__half2*>(&w.w));
    acc[0] += v * f0.x; acc[1] += v * f0.y;
    acc[2] += v * f1.x; acc[3] += v * f1.y;
    acc[4] += v * f2.x; acc[5] += v * f2.y;
    acc[6] += v * f3.x; acc[7] += v * f3.y;
}

__global__ void __launch_bounds__(256) spmm_f16(
    const int* __restrict__ ptr, const int2* __restrict__ cv,
    const __half* __restrict__ src,
    float* __restrict__ dst,
    __half* __restrict__ dsth, int hoff, int r0, int r1)
{
    int t = blockIdx.x * blockDim.x + threadIdx.x;
    int row = r0 + (t >> 4);
    int lane = threadIdx.x & 15;
    int pair = lane >> 3;
    int q    = lane & 7;
    bool valid = row < r1;

    int s = 0, e = 0;
    if (valid) { s = __ldg(ptr + row); e = __ldg(ptr + row + 1); }

    float acc[8] = {0.f, 0.f, 0.f, 0.f, 0.f, 0.f, 0.f, 0.f};
    const __half2 z2 = __floats2half2_rn(0.f, 0.f);
    int i = s;
    for (; i + 8 <= e; i += 8) {
        int2 a0 = __ldg(cv + i     + pair);
        int2 a1 = __ldg(cv + i + 2 + pair);
        int2 a2 = __ldg(cv + i + 4 + pair);
        int2 a3 = __ldg(cv + i + 6 + pair);
        uint4 w0 = __ldg((const uint4*)(src + (size_t)a0.x * LATDIM) + q);
        uint4 w1 = __ldg((const uint4*)(src + (size_t)a1.x * LATDIM) + q);
        uint4 w2 = __ldg((const uint4*)(src + (size_t)a2.x * LATDIM) + q);
        uint4 w3 = __ldg((const uint4*)(src + (size_t)a3.x * LATDIM) + q);

        __half2 h[4] = {z2, z2, z2, z2};
        hacc4(h, w0, as_h2(a0.y));
        hacc4(h, w1, as_h2(a1.y));
        hacc4(h, w2, as_h2(a2.y));
        hacc4(h, w3, as_h2(a3.y));

        float2 f0 = __half22float2(h[0]);
        float2 f1 = __half22float2(h[1]);
        float2 f2 = __half22float2(h[2]);
        float2 f3 = __half22float2(h[3]);
        acc[0] += f0.x; acc[1] += f0.y;
        acc[2] += f1.x; acc[3] += f1.y;
        acc[4] += f2.x; acc[5] += f2.y;
        acc[6] += f3.x; acc[7] += f3.y;
    }
    for (; i + 2 <= e; i += 2) {
        int2 a = __ldg(cv + i + pair);
        uint4 w = __ldg((const uint4*)(src + (size_t)a.x * LATDIM) + q);
        acc8f(acc, w, __low2float(as_h2(a.y)));
    }
    if (i < e && pair == 0) {
        int2 a = __ldg(cv + i);
        uint4 w = __ldg((const uint4*)(src + (size_t)a.x * LATDIM) + q);
        acc8f(acc, w, __low2float(as_h2(a.y)));
    }

    #pragma unroll
    for (int j = 0; j < 8; j++)
        acc[j] += __shfl_xor_sync(0xffffffffu, acc[j], 8);

    if (valid && pair == 0 && dst != nullptr) {
        float4 lo = make_float4(acc[0], acc[1], acc[2], acc[3]);
        float4 hi = make_float4(acc[4], acc[5], acc[6], acc[7]);
        float4* d = (float4*)(dst + (size_t)row * LATDIM);
        d[2 * q]     = lo;
        d[2 * q + 1] = hi;
    }
    if (valid && pair == 1 && dsth != nullptr) {
        __half2 h0 = __floats2half2_rn(acc[0], acc[1]);
        __half2 h1 = __floats2half2_rn(acc[2], acc[3]);
        __half2 h2 = __floats2half2_rn(acc[4], acc[5]);
        __half2 h3 = __floats2half2_rn(acc[6], acc[7]);
        uint4 pk;
        pk.x = *reinterpret_cast<unsigned*>(&h0);
        pk.y = *reinterpret_cast<unsigned*>(&h1);
        pk.z = *reinterpret_cast<unsigned*>(&h2);
        pk.w = *reinterpret_cast<unsigned*>(&h3);
        ((uint4*)(dsth + (size_t)(row - hoff) * LATDIM))[q] = pk;
    }
}

// fp32-source variant (soc layer 0 only; off the critical path)
__global__ void __launch_bounds__(256) spmm_f32src(
    const int* __restrict__ ptr, const int2* __restrict__ cv,
    const float* __restrict__ src,
    float* __restrict__ dst, __half* __restrict__ dsth, int nrows)
{
    int hw = (blockIdx.x * blockDim.x + threadIdx.x) >> 4;
    int q  = threadIdx.x & 15;
    if (hw >= nrows) return;
    int s = __ldg(ptr + hw);
    int e = __ldg(ptr + hw + 1);
    float4 acc = make_float4(0.f, 0.f, 0.f, 0.f);
    int i = s;
    for (; i + 4 <= e; i += 4) {
        int2 a0 = __ldg(cv + i),     a1 = __ldg(cv + i + 1);
        int2 a2 = __ldg(cv + i + 2), a3 = __ldg(cv + i + 3);
        float4 x0 = __ldg((const float4*)(src + (size_t)a0.x * LATDIM) + q);
        float4 x1 = __ldg((const float4*)(src + (size_t)a1.x * LATDIM) + q);
        float4 x2 = __ldg((const float4*)(src + (size_t)a2.x * LATDIM) + q);
        float4 x3 = __ldg((const float4*)(src + (size_t)a3.x * LATDIM) + q);
        float v0 = __low2float(as_h2(a0.y)), v1 = __low2float(as_h2(a1.y));
        float v2 = __low2float(as_h2(a2.y)), v3 = __low2float(as_h2(a3.y));
        acc.x += v0 * x0.x; acc.y += v0 * x0.y; acc.z += v0 * x0.z; acc.w += v0 * x0.w;
        acc.x += v1 * x1.x; acc.y += v1 * x1.y; acc.z += v1 * x1.z; acc.w += v1 * x1.w;
        acc.x += v2 * x2.x; acc.y += v2 * x2.y; acc.z += v2 * x2.z; acc.w += v2 * x2.w;
        acc.x += v3 * x3.x; acc.y += v3 * x3.y; acc.z += v3 * x3.z; acc.w += v3 * x3.w;
    }
    for (; i < e; i++) {
        int2 a = __ldg(cv + i);
        float4 x = __ldg((const float4*)(src + (size_t)a.x * LATDIM) + q);
        float v = __low2float(as_h2(a.y));
        acc.x += v * x.x; acc.y += v * x.y; acc.z += v * x.z; acc.w += v * x.w;
    }
    ((float4*)(dst + (size_t)hw * LATDIM))[q] = acc;
    __half2 h0 = __floats2half2_rn(acc.x, acc.y);
    __half2 h1 = __floats2half2_rn(acc.z, acc.w);
    uint2 pk;
    pk.x = *reinterpret_cast<unsigned*>(&h0);
    pk.y = *reinterpret_cast<unsigned*>(&h1);
    ((uint2*)(dsth + (size_t)hw * LATDIM))[q] = pk;
}

// ---------------------------------------------------------------------------
// Gate + fuse (fp32 in, fp32 out + optional fp16 out into comb user region)
// ---------------------------------------------------------------------------
__global__ void gate_fuse(const float* __restrict__ uu, const float* __restrict__ hi,
                          const float* __restrict__ Wg, const float* __restrict__ bg,
                          float* __restrict__ out, __half* __restrict__ outh)
{
    int gt = blockIdx.x * blockDim.x + threadIdx.x;
    int u = gt >> 5;
    int lane = threadIdx.x & 31;
    if (u >= N_USER) return;

    float2 za = ((const float2*)(uu + (size_t)u * LATDIM))[lane];
    float2 ha = ((const float2*)(hi + (size_t)u * LATDIM))[lane];

    int d = 2 * lane;
    float p0 = za.x * Wg[d]       + za.y * Wg[d + 1]
             + ha.x * Wg[64 + d]  + ha.y * Wg[64 + d + 1];
    float p1 = za.x * Wg[128 + d]      + za.y * Wg[128 + d + 1]
             + ha.x * Wg[128 + 64 + d] + ha.y * Wg[128 + 64 + d + 1];
    #pragma unroll
    for (int o = 16; o; o >>= 1) {
        p0 += __shfl_xor_sync(0xffffffffu, p0, o);
        p1 += __shfl_xor_sync(0xffffffffu, p1, o);
    }
    float l0 = p0 + bg[0];
    float l1 = p1 + bg[1];
    l0 = l0 > 0.f ? l0 : 0.01f * l0;
    l1 = l1 > 0.f ? l1 : 0.01f * l1;
    float mx = fmaxf(l0, l1);
    float e0 = __expf(l0 - mx), e1 = __expf(l1 - mx);
    float inv = 1.f / (e0 + e1);
    float m0 = e0 * inv, m1 = e1 * inv;

    float2 o2 = make_float2(za.x * m0 + ha.x * m1, za.y * m0 + ha.y * m1);
    ((float2*)(out + (size_t)u * LATDIM))[lane] = o2;
    if (outh != nullptr)
        ((__half2*)(outh + (size_t)u * LATDIM))[lane] = __float22half2_rn(o2);
}

// ---------------------------------------------------------------------------
// 5-way attention readout — fp32 sources (user side)
// ---------------------------------------------------------------------------
__global__ void attn5(const float* __restrict__ f0, const float* __restrict__ f1,
                      const float* __restrict__ f2, const float* __restrict__ f3,
                      const float* __restrict__ f4,
                      const float* __restrict__ W, const float* __restrict__ b,
                      float* __restrict__ out, int N)
{
    __shared__ float sW[5 * 320];
    __shared__ float sb[5];
    for (int i = threadIdx.x; i < 5 * 320; i += blockDim.x) sW[i] = W[i];
    if (threadIdx.x < 5) sb[threadIdx.x] = b[threadIdx.x];
    __syncthreads();

    int gt = blockIdx.x * blockDim.x + threadIdx.x;
    int u = gt >> 5;
    int lane = threadIdx.x & 31;
    if (u >= N) return;

    const float* fp[5] = {f0, f1, f2, f3, f4};
    float2 f[5];
    #pragma unroll
    for (int k = 0; k < 5; k++)
        f[k] = ((const float2*)(fp[k] + (size_t)u * LATDIM))[lane];

    int d = 2 * lane;
    float p[5];
    #pragma unroll
    for (int j = 0; j < 5; j++) {
        float acc = 0.f;
        #pragma unroll
        for (int k = 0; k < 5; k++) {
            acc += f[k].x * sW[j * 320 + k * 64 + d];
            acc += f[k].y * sW[j * 320 + k * 64 + d + 1];
        }
        p[j] = acc;
    }
    #pragma unroll
    for (int j = 0; j < 5; j++)
        #pragma unroll
        for (int o = 16; o; o >>= 1)
            p[j] += __shfl_xor_sync(0xffffffffu, p[j], o);

    float mx = -1e30f;
    #pragma unroll
    for (int j = 0; j < 5; j++) {
        float l = p[j] + sb[j];
        l = l > 0.f ? l : 0.01f * l;
        p[j] = l;
        mx = fmaxf(mx, l);
    }
    float se = 0.f;
    #pragma unroll
    for (int j = 0; j < 5; j++) { p[j] = __expf(p[j] - mx); se += p[j]; }
    float inv = 1.f / se;

    float2 o2 = make_float2(0.f, 0.f);
    #pragma unroll
    for (int k = 0; k < 5; k++) {
        float w = p[k] * inv;
        o2.x += w * f[k].x;
        o2.y += w * f[k].y;
    }
    ((float2*)(out + (size_t)u * LATDIM))[lane] = o2;
}

// ---------------------------------------------------------------------------
// 5-way attention readout — item side: f0 fp32 (iE), f1..f4 fp16 shadows
// ---------------------------------------------------------------------------
__global__ void attn5h(const float* __restrict__ f0,
                       const __half* __restrict__ h1, const __half* __restrict__ h2,
                       const __half* __restrict__ h3, const __half* __restrict__ h4,
                       const float* __restrict__ W, const float* __restrict__ b,
                       float* __restrict__ out, int N)
{
    __shared__ float sW[5 * 320];
    __shared__ float sb[5];
    for (int i = threadIdx.x; i < 5 * 320; i += blockDim.x) sW[i] = W[i];
    if (threadIdx.x < 5) sb[threadIdx.x] = b[threadIdx.x];
    __syncthreads();

    int gt = blockIdx.x * blockDim.x + threadIdx.x;
    int u = gt >> 5;
    int lane = threadIdx.x & 31;
    if (u >= N) return;

    float2 f[5];
    f[0] = ((const float2*)(f0 + (size_t)u * LATDIM))[lane];
    const __half* hp[4] = {h1, h2, h3, h4};
    #pragma unroll
    for (int k = 0; k < 4; k++)
        f[k + 1] = __half22float2(((const __half2*)(hp[k] + (size_t)u * LATDIM))[lane]);

    int d = 2 * lane;
    float p[5];
    #pragma unroll
    for (int j = 0; j < 5; j++) {
        float acc = 0.f;
        #pragma unroll
        for (int k = 0; k < 5; k++) {
            acc += f[k].x * sW[j * 320 + k * 64 + d];
            acc += f[k].y * sW[j * 320 + k * 64 + d + 1];
        }
        p[j] = acc;
    }
    #pragma unroll
    for (int j = 0; j < 5; j++)
        #pragma unroll
        for (int o = 16; o; o >>= 1)
            p[j] += __shfl_xor_sync(0xffffffffu, p[j], o);

    float mx = -1e30f;
    #pragma unroll
    for (int j = 0; j < 5; j++) {
        float l = p[j] + sb[j];
        l = l > 0.f ? l : 0.01f * l;
        p[j] = l;
        mx = fmaxf(mx, l);
    }
    float se = 0.f;
    #pragma unroll
    for (int j = 0; j < 5; j++) { p[j] = __expf(p[j] - mx); se += p[j]; }
    float inv = 1.f / se;

    float2 o2 = make_float2(0.f, 0.f);
    #pragma unroll
    for (int k = 0; k < 5; k++) {
        float w = p[k] * inv;
        o2.x += w * f[k].x;
        o2.y += w * f[k].y;
    }
    ((float2*)(out + (size_t)u * LATDIM))[lane] = o2;
}

// ---------------------------------------------------------------------------

extern "C" void kernel_launch(void* const* d_in, const int* in_sizes, int n_in,
                              void* d_out, int out_size)
{
    const float* uE  = (const float*)d_in[0];
    const float* iE  = (const float*)d_in[1];
    const float* Wg  = (const float*)d_in[2];
    const float* bg  = (const float*)d_in[3];
    const float* WL1 = (const float*)d_in[4];
    const float* bL1 = (const float*)d_in[5];
    const float* WL2 = (const float*)d_in[6];
    const float* bL2 = (const float*)d_in[7];
    const int*   ir  = (const int*)d_in[8];
    const int*   ic  = (const int*)d_in[9];
    const float* iv  = (const float*)d_in[10];
    const int*   sr  = (const int*)d_in[11];
    const int*   sc  = (const int*)d_in[12];
    const float* sv  = (const float*)d_in[13];
    float* out = (float*)d_out;

    float *socB, *intU, *fuB;
    __half *combB, *socH, *it3;
    cudaGetSymbolAddress((void**)&socB,  g_soc);
    cudaGetSymbolAddress((void**)&intU,  g_interU);
    cudaGetSymbolAddress((void**)&fuB,   g_fusedU);
    cudaGetSymbolAddress((void**)&combB, g_comb);
    cudaGetSymbolAddress((void**)&socH,  g_soch);
    cudaGetSymbolAddress((void**)&it3,   g_it3);

    int *icnt, *icur, *iptr, *ibs, *scnt, *scur, *sptr, *sbs;
    int2 *icv, *scv;
    cudaGetSymbolAddress((void**)&icnt, g_icnt);
    cudaGetSymbolAddress((void**)&icur, g_icur);
    cudaGetSymbolAddress((void**)&iptr, g_iptr);
    cudaGetSymbolAddress((void**)&icv,  g_icv);
    cudaGetSymbolAddress((void**)&ibs,  g_ibsum);
    cudaGetSymbolAddress((void**)&scnt, g_scnt);
    cudaGetSymbolAddress((void**)&scur, g_scur);
    cudaGetSymbolAddress((void**)&sptr, g_sptr);
    cudaGetSymbolAddress((void**)&scv,  g_scv);
    cudaGetSymbolAddress((void**)&sbs,  g_sbsum);

    const size_t USZ = (size_t)N_USER * LATDIM;
    const size_t NSZ = (size_t)N_NODE * LATDIM;
    const int NB_I = (N_NODE + 2047) / 2048;   // 147
    const int NB_S = (N_USER + 2047) / 2048;   // 49
    const int nI2 = N_ITEM * LATDIM / 2;       // 6.4M half2

    const int GRID_U = (N_USER * 16 + 255) / 256;   // user-row spmm
    const int GRID_I = (N_ITEM * 16 + 255) / 256;   // item-row spmm

    // --- streams & events ---
    cudaStream_t s2, s3;
    cudaStreamCreateWithFlags(&s2, cudaStreamNonBlocking);
    cudaStreamCreateWithFlags(&s3, cudaStreamNonBlocking);
    cudaEvent_t evFork, evSoc[4], evGate[4], evItem[4], evMain0;
    cudaEventCreateWithFlags(&evFork, cudaEventDisableTiming);
    cudaEventCreateWithFlags(&evMain0, cudaEventDisableTiming);
    for (int k = 0; k < 4; k++) {
        cudaEventCreateWithFlags(&evSoc[k],  cudaEventDisableTiming);
        cudaEventCreateWithFlags(&evGate[k], cudaEventDisableTiming);
        cudaEventCreateWithFlags(&evItem[k], cudaEventDisableTiming);
    }

    cudaEventRecord(evFork, 0);
    cudaStreamWaitEvent(s2, evFork, 0);
    cudaStreamWaitEvent(s3, evFork, 0);

    // === s2: soc CSR build + soc chain (layers 1..4) ===
    hist_rows<<<(E_SOC + 255) / 256, 256, 0, s2>>>(sr, E_SOC, scnt);
    block_sum<<<NB_S, 256, 0, s2>>>(scnt, N_USER, sbs);
    scan_final<<<NB_S, 256, 0, s2>>>(scnt, N_USER, sbs, NB_S, sptr, scur, E_SOC);
    scatter_edges<<<(E_SOC + 255) / 256, 256, 0, s2>>>(sr, sc, sv, E_SOC, scur, scv);

    spmm_f32src<<<GRID_U, 256, 0, s2>>>(sptr, scv, uE, socB, socH, N_USER);
    cudaEventRecord(evSoc[0], s2);
    for (int k = 1; k < 4; k++) {
        spmm_f16<<<GRID_U, 256, 0, s2>>>(
            sptr, scv, socH + (size_t)(k - 1) * USZ,
            socB + (size_t)k * USZ,
            (k < 3) ? socH + (size_t)k * USZ : nullptr, 0, 0, N_USER);
        cudaEventRecord(evSoc[k], s2);
    }

    // === main: gate0 (needs only uE), then inter CSR build (+ iE fp16 conv) ===
    gate_fuse<<<(N_USER * 32 + 255) / 256, 256>>>(
        uE, uE, Wg, bg, fuB, combB);                       // comb[0] user region

    hist_rows<<<(E_INTER + 255) / 256, 256>>>(ir, E_INTER, icnt);
    block_sum<<<NB_I, 256>>>(icnt, N_NODE, ibs);
    scan_final<<<NB_I, 256>>>(icnt, N_NODE, ibs, NB_I, iptr, icur, E_INTER);
    {
        int tot = (E_INTER > nI2) ? E_INTER : nI2;
        scatter_conv<<<(tot + 255) / 256, 256>>>(ir, ic, iv, E_INTER, icur, icv,
                                                 (const float2*)iE,
                                                 (__half2*)(combB + USZ), nI2);
    }
    cudaEventRecord(evMain0, 0);   // comb[0] complete (gate0 + conv) & CSR ready

    // === layers 0..3: user-spmm on main, item-spmm on s3 ===
    for (int k = 0; k < 4; k++) {
        __half* combk = combB + (size_t)k * NSZ;

        // item rows -> comb[k+1] item region (k<3) or it3 (k=3); fp16 only
        cudaStreamWaitEvent(s3, (k == 0) ? evMain0 : evGate[k], 0);
        __half* dsth = (k < 3) ? combB + (size_t)(k + 1) * NSZ + USZ : it3;
        spmm_f16<<<GRID_I, 256, 0, s3>>>(
            iptr, icv, combk, nullptr, dsth, N_USER, N_USER, N_NODE);
        cudaEventRecord(evItem[k], s3);

        // user rows -> intU[k]; fp32 only (main)
        if (k >= 1) cudaStreamWaitEvent(0, evItem[k - 1], 0);
        spmm_f16<<<GRID_U, 256>>>(
            iptr, icv, combk, intU + (size_t)k * USZ, nullptr, 0, 0, N_USER);

        // gate_{k+1} on main (needs soc[k] + intU[k])
        cudaStreamWaitEvent(0, evSoc[k], 0);
        gate_fuse<<<(N_USER * 32 + 255) / 256, 256>>>(
            socB + (size_t)k * USZ, intU + (size_t)k * USZ,
            Wg + (k + 1) * 256, bg + (k + 1) * 2,
            fuB + (size_t)(k + 1) * USZ,
            (k < 3) ? combB + (size_t)(k + 1) * NSZ : nullptr);
        if (k < 3) cudaEventRecord(evGate[k + 1], 0);
    }

    // --- attention readouts ---
    attn5<<<(N_USER * 32 + 255) / 256, 256>>>(
        fuB, fuB + USZ, fuB + 2 * USZ, fuB + 3 * USZ, fuB + 4 * USZ,
        WL1, bL1, out, N_USER);
    cudaStreamWaitEvent(0, evItem[3], 0);
    attn5h<<<(N_ITEM * 32 + 255) / 256, 256>>>(
        iE,
        combB + 1 * NSZ + USZ, combB + 2 * NSZ + USZ, combB + 3 * NSZ + USZ, it3,
        WL2, bL2, out + USZ, N_ITEM);

    // --- cleanup ---
    cudaEventDestroy(evFork);
    cudaEventDestroy(evMain0);
    for (int k = 0; k < 4; k++) {
        cudaEventDestroy(evSoc[k]);
        cudaEventDestroy(evGate[k]);
        cudaEventDestroy(evItem[k]);
    }
    cudaStreamDestroy(s2);
    cudaStreamDestroy(s3);
}

// round 14
// speedup vs baseline: 1.1625x; 1.1625x over previous
#include <cuda_runtime.h>
#include <cuda_fp16.h>

#define N_USER 100000
#define N_ITEM 200000
#define N_NODE 300000
#define LATDIM 64
#define E_INTER 4000000
#define E_SOC   2000000

// fp32 dense scratch (inter keeps USER rows only)
__device__ __align__(256) float g_soc   [4][(size_t)N_USER * LATDIM];
__device__ __align__(256) float g_interU[4][(size_t)N_USER * LATDIM];
__device__ __align__(256) float g_fusedU[5][(size_t)N_USER * LATDIM];

// fp16 gather sources / shadows
// comb[k] = [ fp16(gate_k user rows) ; fp16(inter_{k} item rows) ]
__device__ __align__(256) __half g_comb[4][(size_t)N_NODE * LATDIM];
__device__ __align__(256) __half g_soch[3][(size_t)N_USER * LATDIM];
__device__ __align__(256) __half g_it3 [(size_t)N_ITEM * LATDIM];   // item rows of inter spmm 3

// CSR scratch. cnt arrays self-reset (zeroed by scan_final after use).
__device__ int  g_icnt[N_NODE];
__device__ int  g_icur[N_NODE];
__device__ int  g_iptr[N_NODE + 1];
__device__ __align__(16) int2 g_icv[E_INTER];
__device__ int  g_ibsum[256];

__device__ int  g_scnt[N_USER];
__device__ int  g_scur[N_USER];
__device__ int  g_sptr[N_USER + 1];
__device__ __align__(16) int2 g_scv[E_SOC];
__device__ int  g_sbsum[256];

// ---------------------------------------------------------------------------
// CSR build
// ---------------------------------------------------------------------------
__global__ void hist_rows(const int* __restrict__ rows, int E, int* __restrict__ cnt)
{
    int i = blockIdx.x * blockDim.x + threadIdx.x;
    if (i < E) atomicAdd(&cnt[rows[i]], 1);
}

__global__ void block_sum(const int* __restrict__ cnt, int N, int* __restrict__ bsum)
{
    __shared__ int sh[256];
    int base = blockIdx.x * 2048;
    int s = 0;
    for (int i = threadIdx.x; i < 2048; i += 256) {
        int idx = base + i;
        s += (idx < N) ? cnt[idx] : 0;
    }
    sh[threadIdx.x] = s;
    __syncthreads();
    for (int o = 128; o; o >>= 1) {
        if (threadIdx.x < o) sh[threadIdx.x] += sh[threadIdx.x + o];
        __syncthreads();
    }
    if (threadIdx.x == 0) bsum[blockIdx.x] = sh[0];
}

__global__ void scan_final(int* __restrict__ cnt, int N,
                           const int* __restrict__ bsum, int NB,
                           int* __restrict__ ptr, int* __restrict__ cur, int E)
{
    __shared__ int shb[256];
    __shared__ int sh[256];
    int t = threadIdx.x;

    shb[t] = (t < NB) ? bsum[t] : 0;
    __syncthreads();
    for (int o = 1; o < 256; o <<= 1) {
        int y = (t >= o) ? shb[t - o] : 0;
        __syncthreads();
        shb[t] += y;
        __syncthreads();
    }
    int block_off = (blockIdx.x == 0) ? 0 : shb[blockIdx.x - 1];

    int base = blockIdx.x * 2048 + t * 8;
    int loc[8];
    int s = 0;
    #pragma unroll
    for (int j = 0; j < 8; j++) {
        int idx = base + j;
        loc[j] = (idx < N) ? cnt[idx] : 0;
        if (idx < N) cnt[idx] = 0;           // self-reset for next call
        s += loc[j];
    }
    sh[t] = s;
    __syncthreads();
    for (int o = 1; o < 256; o <<= 1) {
        int y = (t >= o) ? sh[t - o] : 0;
        __syncthreads();
        sh[t] += y;
        __syncthreads();
    }
    int run = block_off + sh[t] - s;
    #pragma unroll
    for (int j = 0; j < 8; j++) {
        int idx = base + j;
        if (idx < N) { ptr[idx] = run; cur[idx] = run; run += loc[j]; }
    }
    if (blockIdx.x == 0 && t == 0) ptr[N] = E;
}

__global__ void scatter_edges(const int* __restrict__ rows, const int* __restrict__ cols,
                              const float* __restrict__ vals, int E,
                              int* __restrict__ cur, int2* __restrict__ cv)
{
    int i = blockIdx.x * blockDim.x + threadIdx.x;
    if (i >= E) return;
    int p = atomicAdd(&cur[rows[i]], 1);
    cv[p] = make_int2(cols[i], __float_as_int(vals[i]));
}

__global__ void scatter_conv(const int* __restrict__ rows, const int* __restrict__ cols,
                             const float* __restrict__ vals, int E,
                             int* __restrict__ cur, int2* __restrict__ cv,
                             const float2* __restrict__ iE2, __half2* __restrict__ dst2,
                             int nI2)
{
    int i = blockIdx.x * blockDim.x + threadIdx.x;
    if (i < E) {
        int p = atomicAdd(&cur[rows[i]], 1);
        cv[p] = make_int2(cols[i], __float_as_int(vals[i]));
    }
    if (i < nI2) dst2[i] = __float22half2_rn(iE2[i]);
}

// ---------------------------------------------------------------------------
// CSR SpMM (R12 best): 16 lanes/row, pair-lane split; row range [r0, r1).
//   pair = lane>>3 processes 2 edges of the same row concurrently; q = lane&7
//   indexes a uint4 (16B) of the 128B fp16 source row. Combine via shfl_xor(8).
//   fp32 accumulate (F2F + FFMA). fp32 store by pair 0 iff dst != null;
//   fp16 store by pair 1 iff dsth != null (indexed by row - hoff).
// ---------------------------------------------------------------------------
__device__ __forceinline__ void acc8(float* acc, uint4 w, float v)
{
    float2 f0 = __half22float2(*reinterpret_cast<__half2*>(&w.x));
    float2 f1 = __half22float2(*reinterpret_cast<__half2*>(&w.y));
    float2 f2 = __half22float2(*reinterpret_cast<__half2*>(&w.z));
    float2 f3 = __half22float2(*reinterpret_cast<__half2*>(&w.w));
    acc[0] += v * f0.x; acc[1] += v * f0.y;
    acc[2] += v * f1.x; acc[3] += v * f1.y;
    acc[4] += v * f2.x; acc[5] += v * f2.y;
    acc[6] += v * f3.x; acc[7] += v * f3.y;
}

__global__ void __launch_bounds__(256) spmm_f16(
    const int* __restrict__ ptr, const int2* __restrict__ cv,
    const __half* __restrict__ src,
    float* __restrict__ dst,
    __half* __restrict__ dsth, int hoff, int r0, int r1)
{
    int t = blockIdx.x * blockDim.x + threadIdx.x;
    int row = r0 + (t >> 4);
    int lane = threadIdx.x & 15;
    int pair = lane >> 3;
    int q    = lane & 7;
    bool valid = row < r1;

    int s = 0, e = 0;
    if (valid) { s = __ldg(ptr + row); e = __ldg(ptr + row + 1); }

    float acc[8] = {0.f, 0.f, 0.f, 0.f, 0.f, 0.f, 0.f, 0.f};
    int i = s;
    for (; i + 8 <= e; i += 8) {
        int2 a0 = __ldg(cv + i     + pair);
        int2 a1 = __ldg(cv + i + 2 + pair);
        int2 a2 = __ldg(cv + i + 4 + pair);
        int2 a3 = __ldg(cv + i + 6 + pair);
        uint4 w0 = __ldg((const uint4*)(src + (size_t)a0.x * LATDIM) + q);
        uint4 w1 = __ldg((const uint4*)(src + (size_t)a1.x * LATDIM) + q);
        uint4 w2 = __ldg((const uint4*)(src + (size_t)a2.x * LATDIM) + q);
        uint4 w3 = __ldg((const uint4*)(src + (size_t)a3.x * LATDIM) + q);
        acc8(acc, w0, __int_as_float(a0.y));
        acc8(acc, w1, __int_as_float(a1.y));
        acc8(acc, w2, __int_as_float(a2.y));
        acc8(acc, w3, __int_as_float(a3.y));
    }
    for (; i + 2 <= e; i += 2) {
        int2 a = __ldg(cv + i + pair);
        uint4 w = __ldg((const uint4*)(src + (size_t)a.x * LATDIM) + q);
        acc8(acc, w, __int_as_float(a.y));
    }
    if (i < e && pair == 0) {
        int2 a = __ldg(cv + i);
        uint4 w = __ldg((const uint4*)(src + (size_t)a.x * LATDIM) + q);
        acc8(acc, w, __int_as_float(a.y));
    }

    #pragma unroll
    for (int j = 0; j < 8; j++)
        acc[j] += __shfl_xor_sync(0xffffffffu, acc[j], 8);

    if (valid && pair == 0 && dst != nullptr) {
        float4 lo = make_float4(acc[0], acc[1], acc[2], acc[3]);
        float4 hi = make_float4(acc[4], acc[5], acc[6], acc[7]);
        float4* d = (float4*)(dst + (size_t)row * LATDIM);
        d[2 * q]     = lo;
        d[2 * q + 1] = hi;
    }
    if (valid && pair == 1 && dsth != nullptr) {
        __half2 h0 = __floats2half2_rn(acc[0], acc[1]);
        __half2 h1 = __floats2half2_rn(acc[2], acc[3]);
        __half2 h2 = __floats2half2_rn(acc[4], acc[5]);
        __half2 h3 = __floats2half2_rn(acc[6], acc[7]);
        uint4 pk;
        pk.x = *reinterpret_cast<unsigned*>(&h0);
        pk.y = *reinterpret_cast<unsigned*>(&h1);
        pk.z = *reinterpret_cast<unsigned*>(&h2);
        pk.w = *reinterpret_cast<unsigned*>(&h3);
        ((uint4*)(dsth + (size_t)(row - hoff) * LATDIM))[q] = pk;
    }
}

// fp32-source variant (soc layer 0 only; off the critical path)
__global__ void __launch_bounds__(256) spmm_f32src(
    const int* __restrict__ ptr, const int2* __restrict__ cv,
    const float* __restrict__ src,
    float* __restrict__ dst, __half* __restrict__ dsth, int nrows)
{
    int hw = (blockIdx.x * blockDim.x + threadIdx.x) >> 4;
    int q  = threadIdx.x & 15;
    if (hw >= nrows) return;
    int s = __ldg(ptr + hw);
    int e = __ldg(ptr + hw + 1);
    float4 acc = make_float4(0.f, 0.f, 0.f, 0.f);
    int i = s;
    for (; i + 4 <= e; i += 4) {
        int2 a0 = __ldg(cv + i),     a1 = __ldg(cv + i + 1);
        int2 a2 = __ldg(cv + i + 2), a3 = __ldg(cv + i + 3);
        float4 x0 = __ldg((const float4*)(src + (size_t)a0.x * LATDIM) + q);
        float4 x1 = __ldg((const float4*)(src + (size_t)a1.x * LATDIM) + q);
        float4 x2 = __ldg((const float4*)(src + (size_t)a2.x * LATDIM) + q);
        float4 x3 = __ldg((const float4*)(src + (size_t)a3.x * LATDIM) + q);
        float v0 = __int_as_float(a0.y), v1 = __int_as_float(a1.y);
        float v2 = __int_as_float(a2.y), v3 = __int_as_float(a3.y);
        acc.x += v0 * x0.x; acc.y += v0 * x0.y; acc.z += v0 * x0.z; acc.w += v0 * x0.w;
        acc.x += v1 * x1.x; acc.y += v1 * x1.y; acc.z += v1 * x1.z; acc.w += v1 * x1.w;
        acc.x += v2 * x2.x; acc.y += v2 * x2.y; acc.z += v2 * x2.z; acc.w += v2 * x2.w;
        acc.x += v3 * x3.x; acc.y += v3 * x3.y; acc.z += v3 * x3.z; acc.w += v3 * x3.w;
    }
    for (; i < e; i++) {
        int2 a = __ldg(cv + i);
        float4 x = __ldg((const float4*)(src + (size_t)a.x * LATDIM) + q);
        float v = __int_as_float(a.y);
        acc.x += v * x.x; acc.y += v * x.y; acc.z += v * x.z; acc.w += v * x.w;
    }
    ((float4*)(dst + (size_t)hw * LATDIM))[q] = acc;
    __half2 h0 = __floats2half2_rn(acc.x, acc.y);
    __half2 h1 = __floats2half2_rn(acc.z, acc.w);
    uint2 pk;
    pk.x = *reinterpret_cast<unsigned*>(&h0);
    pk.y = *reinterpret_cast<unsigned*>(&h1);
    ((uint2*)(dsth + (size_t)hw * LATDIM))[q] = pk;
}

// ---------------------------------------------------------------------------
// Gate + fuse (fp32 in, fp32 out + optional fp16 out into comb user region)
// ---------------------------------------------------------------------------
__global__ void gate_fuse(const float* __restrict__ uu, const float* __restrict__ hi,
                          const float* __restrict__ Wg, const float* __restrict__ bg,
                          float* __restrict__ out, __half* __restrict__ outh)
{
    int gt = blockIdx.x * blockDim.x + threadIdx.x;
    int u = gt >> 5;
    int lane = threadIdx.x & 31;
    if (u >= N_USER) return;

    float2 za = ((const float2*)(uu + (size_t)u * LATDIM))[lane];
    float2 ha = ((const float2*)(hi + (size_t)u * LATDIM))[lane];

    int d = 2 * lane;
    float p0 = za.x * Wg[d]       + za.y * Wg[d + 1]
             + ha.x * Wg[64 + d]  + ha.y * Wg[64 + d + 1];
    float p1 = za.x * Wg[128 + d]      + za.y * Wg[128 + d + 1]
             + ha.x * Wg[128 + 64 + d] + ha.y * Wg[128 + 64 + d + 1];
    #pragma unroll
    for (int o = 16; o; o >>= 1) {
        p0 += __shfl_xor_sync(0xffffffffu, p0, o);
        p1 += __shfl_xor_sync(0xffffffffu, p1, o);
    }
    float l0 = p0 + bg[0];
    float l1 = p1 + bg[1];
    l0 = l0 > 0.f ? l0 : 0.01f * l0;
    l1 = l1 > 0.f ? l1 : 0.01f * l1;
    float mx = fmaxf(l0, l1);
    float e0 = __expf(l0 - mx), e1 = __expf(l1 - mx);
    float inv = 1.f / (e0 + e1);
    float m0 = e0 * inv, m1 = e1 * inv;

    float2 o2 = make_float2(za.x * m0 + ha.x * m1, za.y * m0 + ha.y * m1);
    ((float2*)(out + (size_t)u * LATDIM))[lane] = o2;
    if (outh != nullptr)
        ((__half2*)(outh + (size_t)u * LATDIM))[lane] = __float22half2_rn(o2);
}

// ---------------------------------------------------------------------------
// 5-way attention readout — fp32 sources (user side)
// ---------------------------------------------------------------------------
__global__ void attn5(const float* __restrict__ f0, const float* __restrict__ f1,
                      const float* __restrict__ f2, const float* __restrict__ f3,
                      const float* __restrict__ f4,
                      const float* __restrict__ W, const float* __restrict__ b,
                      float* __restrict__ out, int N)
{
    __shared__ float sW[5 * 320];
    __shared__ float sb[5];
    for (int i = threadIdx.x; i < 5 * 320; i += blockDim.x) sW[i] = W[i];
    if (threadIdx.x < 5) sb[threadIdx.x] = b[threadIdx.x];
    __syncthreads();

    int gt = blockIdx.x * blockDim.x + threadIdx.x;
    int u = gt >> 5;
    int lane = threadIdx.x & 31;
    if (u >= N) return;

    const float* fp[5] = {f0, f1, f2, f3, f4};
    float2 f[5];
    #pragma unroll
    for (int k = 0; k < 5; k++)
        f[k] = ((const float2*)(fp[k] + (size_t)u * LATDIM))[lane];

    int d = 2 * lane;
    float p[5];
    #pragma unroll
    for (int j = 0; j < 5; j++) {
        float acc = 0.f;
        #pragma unroll
        for (int k = 0; k < 5; k++) {
            acc += f[k].x * sW[j * 320 + k * 64 + d];
            acc += f[k].y * sW[j * 320 + k * 64 + d + 1];
        }
        p[j] = acc;
    }
    #pragma unroll
    for (int j = 0; j < 5; j++)
        #pragma unroll
        for (int o = 16; o; o >>= 1)
            p[j] += __shfl_xor_sync(0xffffffffu, p[j], o);

    float mx = -1e30f;
    #pragma unroll
    for (int j = 0; j < 5; j++) {
        float l = p[j] + sb[j];
        l = l > 0.f ? l : 0.01f * l;
        p[j] = l;
        mx = fmaxf(mx, l);
    }
    float se = 0.f;
    #pragma unroll
    for (int j = 0; j < 5; j++) { p[j] = __expf(p[j] - mx); se += p[j]; }
    float inv = 1.f / se;

    float2 o2 = make_float2(0.f, 0.f);
    #pragma unroll
    for (int k = 0; k < 5; k++) {
        float w = p[k] * inv;
        o2.x += w * f[k].x;
        o2.y += w * f[k].y;
    }
    ((float2*)(out + (size_t)u * LATDIM))[lane] = o2;
}

// ---------------------------------------------------------------------------
// 5-way attention readout — item side: f0 fp32 (iE), f1..f4 fp16 shadows
// ---------------------------------------------------------------------------
__global__ void attn5h(const float* __restrict__ f0,
                       const __half* __restrict__ h1, const __half* __restrict__ h2,
                       const __half* __restrict__ h3, const __half* __restrict__ h4,
                       const float* __restrict__ W, const float* __restrict__ b,
                       float* __restrict__ out, int N)
{
    __shared__ float sW[5 * 320];
    __shared__ float sb[5];
    for (int i = threadIdx.x; i < 5 * 320; i += blockDim.x) sW[i] = W[i];
    if (threadIdx.x < 5) sb[threadIdx.x] = b[threadIdx.x];
    __syncthreads();

    int gt = blockIdx.x * blockDim.x + threadIdx.x;
    int u = gt >> 5;
    int lane = threadIdx.x & 31;
    if (u >= N) return;

    float2 f[5];
    f[0] = ((const float2*)(f0 + (size_t)u * LATDIM))[lane];
    const __half* hp[4] = {h1, h2, h3, h4};
    #pragma unroll
    for (int k = 0; k < 4; k++)
        f[k + 1] = __half22float2(((const __half2*)(hp[k] + (size_t)u * LATDIM))[lane]);

    int d = 2 * lane;
    float p[5];
    #pragma unroll
    for (int j = 0; j < 5; j++) {
        float acc = 0.f;
        #pragma unroll
        for (int k = 0; k < 5; k++) {
            acc += f[k].x * sW[j * 320 + k * 64 + d];
            acc += f[k].y * sW[j * 320 + k * 64 + d + 1];
        }
        p[j] = acc;
    }
    #pragma unroll
    for (int j = 0; j < 5; j++)
        #pragma unroll
        for (int o = 16; o; o >>= 1)
            p[j] += __shfl_xor_sync(0xffffffffu, p[j], o);

    float mx = -1e30f;
    #pragma unroll
    for (int j = 0; j < 5; j++) {
        float l = p[j] + sb[j];
        l = l > 0.f ? l : 0.01f * l;
        p[j] = l;
        mx = fmaxf(mx, l);
    }
    float se = 0.f;
    #pragma unroll
    for (int j = 0; j < 5; j++) { p[j] = __expf(p[j] - mx); se += p[j]; }
    float inv = 1.f / se;

    float2 o2 = make_float2(0.f, 0.f);
    #pragma unroll
    for (int k = 0; k < 5; k++) {
        float w = p[k] * inv;
        o2.x += w * f[k].x;
        o2.y += w * f[k].y;
    }
    ((float2*)(out + (size_t)u * LATDIM))[lane] = o2;
}

// ---------------------------------------------------------------------------

extern "C" void kernel_launch(void* const* d_in, const int* in_sizes, int n_in,
                              void* d_out, int out_size)
{
    const float* uE  = (const float*)d_in[0];
    const float* iE  = (const float*)d_in[1];
    const float* Wg  = (const float*)d_in[2];
    const float* bg  = (const float*)d_in[3];
    const float* WL1 = (const float*)d_in[4];
    const float* bL1 = (const float*)d_in[5];
    const float* WL2 = (const float*)d_in[6];
    const float* bL2 = (const float*)d_in[7];
    const int*   ir  = (const int*)d_in[8];
    const int*   ic  = (const int*)d_in[9];
    const float* iv  = (const float*)d_in[10];
    const int*   sr  = (const int*)d_in[11];
    const int*   sc  = (const int*)d_in[12];
    const float* sv  = (const float*)d_in[13];
    float* out = (float*)d_out;

    float *socB, *intU, *fuB;
    __half *combB, *socH, *it3;
    cudaGetSymbolAddress((void**)&socB,  g_soc);
    cudaGetSymbolAddress((void**)&intU,  g_interU);
    cudaGetSymbolAddress((void**)&fuB,   g_fusedU);
    cudaGetSymbolAddress((void**)&combB, g_comb);
    cudaGetSymbolAddress((void**)&socH,  g_soch);
    cudaGetSymbolAddress((void**)&it3,   g_it3);

    int *icnt, *icur, *iptr, *ibs, *scnt, *scur, *sptr, *sbs;
    int2 *icv, *scv;
    cudaGetSymbolAddress((void**)&icnt, g_icnt);
    cudaGetSymbolAddress((void**)&icur, g_icur);
    cudaGetSymbolAddress((void**)&iptr, g_iptr);
    cudaGetSymbolAddress((void**)&icv,  g_icv);
    cudaGetSymbolAddress((void**)&ibs,  g_ibsum);
    cudaGetSymbolAddress((void**)&scnt, g_scnt);
    cudaGetSymbolAddress((void**)&scur, g_scur);
    cudaGetSymbolAddress((void**)&sptr, g_sptr);
    cudaGetSymbolAddress((void**)&scv,  g_scv);
    cudaGetSymbolAddress((void**)&sbs,  g_sbsum);

    const size_t USZ = (size_t)N_USER * LATDIM;
    const size_t NSZ = (size_t)N_NODE * LATDIM;
    const int NB_I = (N_NODE + 2047) / 2048;   // 147
    const int NB_S = (N_USER + 2047) / 2048;   // 49
    const int nI2 = N_ITEM * LATDIM / 2;       // 6.4M half2

    const int GRID_U = (N_USER * 16 + 255) / 256;   // user-row spmm
    const int GRID_I = (N_ITEM * 16 + 255) / 256;   // item-row spmm

    // --- streams & events ---
    cudaStream_t s2, s3;
    cudaStreamCreateWithFlags(&s2, cudaStreamNonBlocking);
    cudaStreamCreateWithFlags(&s3, cudaStreamNonBlocking);
    cudaEvent_t evFork, evSoc[4], evGate[4], evItem[4], evMain0, evAttnI;
    cudaEventCreateWithFlags(&evFork, cudaEventDisableTiming);
    cudaEventCreateWithFlags(&evMain0, cudaEventDisableTiming);
    cudaEventCreateWithFlags(&evAttnI, cudaEventDisableTiming);
    for (int k = 0; k < 4; k++) {
        cudaEventCreateWithFlags(&evSoc[k],  cudaEventDisableTiming);
        cudaEventCreateWithFlags(&evGate[k], cudaEventDisableTiming);
        cudaEventCreateWithFlags(&evItem[k], cudaEventDisableTiming);
    }

    cudaEventRecord(evFork, 0);
    cudaStreamWaitEvent(s2, evFork, 0);
    cudaStreamWaitEvent(s3, evFork, 0);

    // === s2: soc CSR build + soc chain (layers 1..4) ===
    hist_rows<<<(E_SOC + 255) / 256, 256, 0, s2>>>(sr, E_SOC, scnt);
    block_sum<<<NB_S, 256, 0, s2>>>(scnt, N_USER, sbs);
    scan_final<<<NB_S, 256, 0, s2>>>(scnt, N_USER, sbs, NB_S, sptr, scur, E_SOC);
    scatter_edges<<<(E_SOC + 255) / 256, 256, 0, s2>>>(sr, sc, sv, E_SOC, scur, scv);

    spmm_f32src<<<GRID_U, 256, 0, s2>>>(sptr, scv, uE, socB, socH, N_USER);
    cudaEventRecord(evSoc[0], s2);
    for (int k = 1; k < 4; k++) {
        spmm_f16<<<GRID_U, 256, 0, s2>>>(
            sptr, scv, socH + (size_t)(k - 1) * USZ,
            socB + (size_t)k * USZ,
            (k < 3) ? socH + (size_t)k * USZ : nullptr, 0, 0, N_USER);
        cudaEventRecord(evSoc[k], s2);
    }

    // === main: gate0 (needs only uE), then inter CSR build (+ iE fp16 conv) ===
    gate_fuse<<<(N_USER * 32 + 255) / 256, 256>>>(
        uE, uE, Wg, bg, fuB, combB);                       // comb[0] user region

    hist_rows<<<(E_INTER + 255) / 256, 256>>>(ir, E_INTER, icnt);
    block_sum<<<NB_I, 256>>>(icnt, N_NODE, ibs);
    scan_final<<<NB_I, 256>>>(icnt, N_NODE, ibs, NB_I, iptr, icur, E_INTER);
    {
        int tot = (E_INTER > nI2) ? E_INTER : nI2;
        scatter_conv<<<(tot + 255) / 256, 256>>>(ir, ic, iv, E_INTER, icur, icv,
                                                 (const float2*)iE,
                                                 (__half2*)(combB + USZ), nI2);
    }
    cudaEventRecord(evMain0, 0);   // comb[0] complete (gate0 + conv) & CSR ready

    // === layers 0..3: user-spmm on main, item-spmm on s3 ===
    for (int k = 0; k < 4; k++) {
        __half* combk = combB + (size_t)k * NSZ;

        // item rows -> comb[k+1] item region (k<3) or it3 (k=3); fp16 only
        cudaStreamWaitEvent(s3, (k == 0) ? evMain0 : evGate[k], 0);
        __half* dsth = (k < 3) ? combB + (size_t)(k + 1) * NSZ + USZ : it3;
        spmm_f16<<<GRID_I, 256, 0, s3>>>(
            iptr, icv, combk, nullptr, dsth, N_USER, N_USER, N_NODE);
        cudaEventRecord(evItem[k], s3);

        // user rows -> intU[k]; fp32 only (main)
        if (k >= 1) cudaStreamWaitEvent(0, evItem[k - 1], 0);
        spmm_f16<<<GRID_U, 256>>>(
            iptr, icv, combk, intU + (size_t)k * USZ, nullptr, 0, 0, N_USER);

        // gate_{k+1} on main (needs soc[k] + intU[k])
        cudaStreamWaitEvent(0, evSoc[k], 0);
        gate_fuse<<<(N_USER * 32 + 255) / 256, 256>>>(
            socB + (size_t)k * USZ, intU + (size_t)k * USZ,
            Wg + (k + 1) * 256, bg + (k + 1) * 2,
            fuB + (size_t)(k + 1) * USZ,
            (k < 3) ? combB + (size_t)(k + 1) * NSZ : nullptr);
        if (k < 3) cudaEventRecord(evGate[k + 1], 0);
    }

    // --- attention readouts: item side on s3 (deps already there), user on main ---
    attn5h<<<(N_ITEM * 32 + 255) / 256, 256, 0, s3>>>(
        iE,
        combB + 1 * NSZ + USZ, combB + 2 * NSZ + USZ, combB + 3 * NSZ + USZ, it3,
        WL2, bL2, out + USZ, N_ITEM);
    cudaEventRecord(evAttnI, s3);

    attn5<<<(N_USER * 32 + 255) / 256, 256>>>(
        fuB, fuB + USZ, fuB + 2 * USZ, fuB + 3 * USZ, fuB + 4 * USZ,
        WL1, bL1, out, N_USER);

    // join s3 back into main (capture fork must be closed on the origin stream)
    cudaStreamWaitEvent(0, evAttnI, 0);

    // --- cleanup ---
    cudaEventDestroy(evFork);
    cudaEventDestroy(evMain0);
    cudaEventDestroy(evAttnI);
    for (int k = 0; k < 4; k++) {
        cudaEventDestroy(evSoc[k]);
        cudaEventDestroy(evGate[k]);
        cudaEventDestroy(evItem[k]);
    }
    cudaStreamDestroy(s2);
    cudaStreamDestroy(s3);
}

// round 15
// speedup vs baseline: 1.1766x; 1.0122x over previous
#include <cuda_runtime.h>
#include <cuda_fp16.h>

#define N_USER 100000
#define N_ITEM 200000
#define N_NODE 300000
#define LATDIM 64
#define E_INTER 4000000
#define E_SOC   2000000

// fp32 dense scratch (inter keeps USER rows only)
__device__ __align__(256) float g_soc   [4][(size_t)N_USER * LATDIM];
__device__ __align__(256) float g_interU[4][(size_t)N_USER * LATDIM];
__device__ __align__(256) float g_fusedU[5][(size_t)N_USER * LATDIM];

// fp16 gather sources / shadows
// comb[k] = [ fp16(gate_k user rows) ; fp16(inter_{k} item rows) ]
__device__ __align__(256) __half g_comb[4][(size_t)N_NODE * LATDIM];
__device__ __align__(256) __half g_soch[3][(size_t)N_USER * LATDIM];
__device__ __align__(256) __half g_it3 [(size_t)N_ITEM * LATDIM];   // item rows of inter spmm 3

// CSR scratch. cnt arrays self-reset (zeroed by scan_final after use).
__device__ int  g_icnt[N_NODE];
__device__ int  g_icur[N_NODE];
__device__ int  g_iptr[N_NODE + 1];
__device__ __align__(16) int2 g_icv[E_INTER];
__device__ int  g_ibsum[256];

__device__ int  g_scnt[N_USER];
__device__ int  g_scur[N_USER];
__device__ int  g_sptr[N_USER + 1];
__device__ __align__(16) int2 g_scv[E_SOC];
__device__ int  g_sbsum[256];

// ---------------------------------------------------------------------------
// CSR build
// ---------------------------------------------------------------------------
__global__ void hist_rows(const int* __restrict__ rows, int E, int* __restrict__ cnt)
{
    int i = blockIdx.x * blockDim.x + threadIdx.x;
    if (i < E) atomicAdd(&cnt[rows[i]], 1);
}

__global__ void block_sum(const int* __restrict__ cnt, int N, int* __restrict__ bsum)
{
    __shared__ int sh[256];
    int base = blockIdx.x * 2048;
    int s = 0;
    for (int i = threadIdx.x; i < 2048; i += 256) {
        int idx = base + i;
        s += (idx < N) ? cnt[idx] : 0;
    }
    sh[threadIdx.x] = s;
    __syncthreads();
    for (int o = 128; o; o >>= 1) {
        if (threadIdx.x < o) sh[threadIdx.x] += sh[threadIdx.x + o];
        __syncthreads();
    }
    if (threadIdx.x == 0) bsum[blockIdx.x] = sh[0];
}

__global__ void scan_final(int* __restrict__ cnt, int N,
                           const int* __restrict__ bsum, int NB,
                           int* __restrict__ ptr, int* __restrict__ cur, int E)
{
    __shared__ int shb[256];
    __shared__ int sh[256];
    int t = threadIdx.x;

    shb[t] = (t < NB) ? bsum[t] : 0;
    __syncthreads();
    for (int o = 1; o < 256; o <<= 1) {
        int y = (t >= o) ? shb[t - o] : 0;
        __syncthreads();
        shb[t] += y;
        __syncthreads();
    }
    int block_off = (blockIdx.x == 0) ? 0 : shb[blockIdx.x - 1];

    int base = blockIdx.x * 2048 + t * 8;
    int loc[8];
    int s = 0;
    #pragma unroll
    for (int j = 0; j < 8; j++) {
        int idx = base + j;
        loc[j] = (idx < N) ? cnt[idx] : 0;
        if (idx < N) cnt[idx] = 0;           // self-reset for next call
        s += loc[j];
    }
    sh[t] = s;
    __syncthreads();
    for (int o = 1; o < 256; o <<= 1) {
        int y = (t >= o) ? sh[t - o] : 0;
        __syncthreads();
        sh[t] += y;
        __syncthreads();
    }
    int run = block_off + sh[t] - s;
    #pragma unroll
    for (int j = 0; j < 8; j++) {
        int idx = base + j;
        if (idx < N) { ptr[idx] = run; cur[idx] = run; run += loc[j]; }
    }
    if (blockIdx.x == 0 && t == 0) ptr[N] = E;
}

__global__ void scatter_edges(const int* __restrict__ rows, const int* __restrict__ cols,
                              const float* __restrict__ vals, int E,
                              int* __restrict__ cur, int2* __restrict__ cv)
{
    int i = blockIdx.x * blockDim.x + threadIdx.x;
    if (i >= E) return;
    int p = atomicAdd(&cur[rows[i]], 1);
    cv[p] = make_int2(cols[i], __float_as_int(vals[i]));
}

__global__ void scatter_conv(const int* __restrict__ rows, const int* __restrict__ cols,
                             const float* __restrict__ vals, int E,
                             int* __restrict__ cur, int2* __restrict__ cv,
                             const float2* __restrict__ iE2, __half2* __restrict__ dst2,
                             int nI2)
{
    int i = blockIdx.x * blockDim.x + threadIdx.x;
    if (i < E) {
        int p = atomicAdd(&cur[rows[i]], 1);
        cv[p] = make_int2(cols[i], __float_as_int(vals[i]));
    }
    if (i < nI2) dst2[i] = __float22half2_rn(iE2[i]);
}

// ---------------------------------------------------------------------------
// CSR SpMM: 16 lanes/row, pair-lane split; row range [r0, r1).
//   pair = lane>>3 processes 2 edges of the same row concurrently; q = lane&7
//   indexes a uint4 (16B) of the 128B fp16 source row. Combine via shfl_xor(8).
//   Tail ladder 8 -> 4 -> 2 -> 1 keeps MLP >= 2 for most tail edges.
// ---------------------------------------------------------------------------
__device__ __forceinline__ void acc8(float* acc, uint4 w, float v)
{
    float2 f0 = __half22float2(*reinterpret_cast<__half2*>(&w.x));
    float2 f1 = __half22float2(*reinterpret_cast<__half2*>(&w.y));
    float2 f2 = __half22float2(*reinterpret_cast<__half2*>(&w.z));
    float2 f3 = __half22float2(*reinterpret_cast<__half2*>(&w.w));
    acc[0] += v * f0.x; acc[1] += v * f0.y;
    acc[2] += v * f1.x; acc[3] += v * f1.y;
    acc[4] += v * f2.x; acc[5] += v * f2.y;
    acc[6] += v * f3.x; acc[7] += v * f3.y;
}

__global__ void __launch_bounds__(256) spmm_f16(
    const int* __restrict__ ptr, const int2* __restrict__ cv,
    const __half* __restrict__ src,
    float* __restrict__ dst,
    __half* __restrict__ dsth, int hoff, int r0, int r1)
{
    int t = blockIdx.x * blockDim.x + threadIdx.x;
    int row = r0 + (t >> 4);
    int lane = threadIdx.x & 15;
    int pair = lane >> 3;
    int q    = lane & 7;
    bool valid = row < r1;

    int s = 0, e = 0;
    if (valid) { s = __ldg(ptr + row); e = __ldg(ptr + row + 1); }

    float acc[8] = {0.f, 0.f, 0.f, 0.f, 0.f, 0.f, 0.f, 0.f};
    int i = s;
    for (; i + 8 <= e; i += 8) {
        int2 a0 = __ldg(cv + i     + pair);
        int2 a1 = __ldg(cv + i + 2 + pair);
        int2 a2 = __ldg(cv + i + 4 + pair);
        int2 a3 = __ldg(cv + i + 6 + pair);
        uint4 w0 = __ldg((const uint4*)(src + (size_t)a0.x * LATDIM) + q);
        uint4 w1 = __ldg((const uint4*)(src + (size_t)a1.x * LATDIM) + q);
        uint4 w2 = __ldg((const uint4*)(src + (size_t)a2.x * LATDIM) + q);
        uint4 w3 = __ldg((const uint4*)(src + (size_t)a3.x * LATDIM) + q);
        acc8(acc, w0, __int_as_float(a0.y));
        acc8(acc, w1, __int_as_float(a1.y));
        acc8(acc, w2, __int_as_float(a2.y));
        acc8(acc, w3, __int_as_float(a3.y));
    }
    if (i + 4 <= e) {                       // 4-edge step: 2 gathers in flight
        int2 a0 = __ldg(cv + i     + pair);
        int2 a1 = __ldg(cv + i + 2 + pair);
        uint4 w0 = __ldg((const uint4*)(src + (size_t)a0.x * LATDIM) + q);
        uint4 w1 = __ldg((const uint4*)(src + (size_t)a1.x * LATDIM) + q);
        acc8(acc, w0, __int_as_float(a0.y));
        acc8(acc, w1, __int_as_float(a1.y));
        i += 4;
    }
    if (i + 2 <= e) {
        int2 a = __ldg(cv + i + pair);
        uint4 w = __ldg((const uint4*)(src + (size_t)a.x * LATDIM) + q);
        acc8(acc, w, __int_as_float(a.y));
        i += 2;
    }
    if (i < e && pair == 0) {
        int2 a = __ldg(cv + i);
        uint4 w = __ldg((const uint4*)(src + (size_t)a.x * LATDIM) + q);
        acc8(acc, w, __int_as_float(a.y));
    }

    #pragma unroll
    for (int j = 0; j < 8; j++)
        acc[j] += __shfl_xor_sync(0xffffffffu, acc[j], 8);

    if (valid && pair == 0 && dst != nullptr) {
        float4 lo = make_float4(acc[0], acc[1], acc[2], acc[3]);
        float4 hi = make_float4(acc[4], acc[5], acc[6], acc[7]);
        float4* d = (float4*)(dst + (size_t)row * LATDIM);
        d[2 * q]     = lo;
        d[2 * q + 1] = hi;
    }
    if (valid && pair == 1 && dsth != nullptr) {
        __half2 h0 = __floats2half2_rn(acc[0], acc[1]);
        __half2 h1 = __floats2half2_rn(acc[2], acc[3]);
        __half2 h2 = __floats2half2_rn(acc[4], acc[5]);
        __half2 h3 = __floats2half2_rn(acc[6], acc[7]);
        uint4 pk;
        pk.x = *reinterpret_cast<unsigned*>(&h0);
        pk.y = *reinterpret_cast<unsigned*>(&h1);
        pk.z = *reinterpret_cast<unsigned*>(&h2);
        pk.w = *reinterpret_cast<unsigned*>(&h3);
        ((uint4*)(dsth + (size_t)(row - hoff) * LATDIM))[q] = pk;
    }
}

// fp32-source variant (soc layer 0 only; off the critical path)
__global__ void __launch_bounds__(256) spmm_f32src(
    const int* __restrict__ ptr, const int2* __restrict__ cv,
    const float* __restrict__ src,
    float* __restrict__ dst, __half* __restrict__ dsth, int nrows)
{
    int hw = (blockIdx.x * blockDim.x + threadIdx.x) >> 4;
    int q  = threadIdx.x & 15;
    if (hw >= nrows) return;
    int s = __ldg(ptr + hw);
    int e = __ldg(ptr + hw + 1);
    float4 acc = make_float4(0.f, 0.f, 0.f, 0.f);
    int i = s;
    for (; i + 4 <= e; i += 4) {
        int2 a0 = __ldg(cv + i),     a1 = __ldg(cv + i + 1);
        int2 a2 = __ldg(cv + i + 2), a3 = __ldg(cv + i + 3);
        float4 x0 = __ldg((const float4*)(src + (size_t)a0.x * LATDIM) + q);
        float4 x1 = __ldg((const float4*)(src + (size_t)a1.x * LATDIM) + q);
        float4 x2 = __ldg((const float4*)(src + (size_t)a2.x * LATDIM) + q);
        float4 x3 = __ldg((const float4*)(src + (size_t)a3.x * LATDIM) + q);
        float v0 = __int_as_float(a0.y), v1 = __int_as_float(a1.y);
        float v2 = __int_as_float(a2.y), v3 = __int_as_float(a3.y);
        acc.x += v0 * x0.x; acc.y += v0 * x0.y; acc.z += v0 * x0.z; acc.w += v0 * x0.w;
        acc.x += v1 * x1.x; acc.y += v1 * x1.y; acc.z += v1 * x1.z; acc.w += v1 * x1.w;
        acc.x += v2 * x2.x; acc.y += v2 * x2.y; acc.z += v2 * x2.z; acc.w += v2 * x2.w;
        acc.x += v3 * x3.x; acc.y += v3 * x3.y; acc.z += v3 * x3.z; acc.w += v3 * x3.w;
    }
    if (i + 2 <= e) {
        int2 a0 = __ldg(cv + i), a1 = __ldg(cv + i + 1);
        float4 x0 = __ldg((const float4*)(src + (size_t)a0.x * LATDIM) + q);
        float4 x1 = __ldg((const float4*)(src + (size_t)a1.x * LATDIM) + q);
        float v0 = __int_as_float(a0.y), v1 = __int_as_float(a1.y);
        acc.x += v0 * x0.x; acc.y += v0 * x0.y; acc.z += v0 * x0.z; acc.w += v0 * x0.w;
        acc.x += v1 * x1.x; acc.y += v1 * x1.y; acc.z += v1 * x1.z; acc.w += v1 * x1.w;
        i += 2;
    }
    if (i < e) {
        int2 a = __ldg(cv + i);
        float4 x = __ldg((const float4*)(src + (size_t)a.x * LATDIM) + q);
        float v = __int_as_float(a.y);
        acc.x += v * x.x; acc.y += v * x.y; acc.z += v * x.z; acc.w += v * x.w;
    }
    ((float4*)(dst + (size_t)hw * LATDIM))[q] = acc;
    __half2 h0 = __floats2half2_rn(acc.x, acc.y);
    __half2 h1 = __floats2half2_rn(acc.z, acc.w);
    uint2 pk;
    pk.x = *reinterpret_cast<unsigned*>(&h0);
    pk.y = *reinterpret_cast<unsigned*>(&h1);
    ((uint2*)(dsth + (size_t)hw * LATDIM))[q] = pk;
}

// ---------------------------------------------------------------------------
// Gate + fuse (fp32 in, fp32 out + optional fp16 out into comb user region)
// ---------------------------------------------------------------------------
__global__ void gate_fuse(const float* __restrict__ uu, const float* __restrict__ hi,
                          const float* __restrict__ Wg, const float* __restrict__ bg,
                          float* __restrict__ out, __half* __restrict__ outh)
{
    int gt = blockIdx.x * blockDim.x + threadIdx.x;
    int u = gt >> 5;
    int lane = threadIdx.x & 31;
    if (u >= N_USER) return;

    float2 za = ((const float2*)(uu + (size_t)u * LATDIM))[lane];
    float2 ha = ((const float2*)(hi + (size_t)u * LATDIM))[lane];

    int d = 2 * lane;
    float p0 = za.x * Wg[d]       + za.y * Wg[d + 1]
             + ha.x * Wg[64 + d]  + ha.y * Wg[64 + d + 1];
    float p1 = za.x * Wg[128 + d]      + za.y * Wg[128 + d + 1]
             + ha.x * Wg[128 + 64 + d] + ha.y * Wg[128 + 64 + d + 1];
    #pragma unroll
    for (int o = 16; o; o >>= 1) {
        p0 += __shfl_xor_sync(0xffffffffu, p0, o);
        p1 += __shfl_xor_sync(0xffffffffu, p1, o);
    }
    float l0 = p0 + bg[0];
    float l1 = p1 + bg[1];
    l0 = l0 > 0.f ? l0 : 0.01f * l0;
    l1 = l1 > 0.f ? l1 : 0.01f * l1;
    float mx = fmaxf(l0, l1);
    float e0 = __expf(l0 - mx), e1 = __expf(l1 - mx);
    float inv = 1.f / (e0 + e1);
    float m0 = e0 * inv, m1 = e1 * inv;

    float2 o2 = make_float2(za.x * m0 + ha.x * m1, za.y * m0 + ha.y * m1);
    ((float2*)(out + (size_t)u * LATDIM))[lane] = o2;
    if (outh != nullptr)
        ((__half2*)(outh + (size_t)u * LATDIM))[lane] = __float22half2_rn(o2);
}

// ---------------------------------------------------------------------------
// 5-way attention readout — fp32 sources (user side)
// ---------------------------------------------------------------------------
__global__ void attn5(const float* __restrict__ f0, const float* __restrict__ f1,
                      const float* __restrict__ f2, const float* __restrict__ f3,
                      const float* __restrict__ f4,
                      const float* __restrict__ W, const float* __restrict__ b,
                      float* __restrict__ out, int N)
{
    __shared__ float sW[5 * 320];
    __shared__ float sb[5];
    for (int i = threadIdx.x; i < 5 * 320; i += blockDim.x) sW[i] = W[i];
    if (threadIdx.x < 5) sb[threadIdx.x] = b[threadIdx.x];
    __syncthreads();

    int gt = blockIdx.x * blockDim.x + threadIdx.x;
    int u = gt >> 5;
    int lane = threadIdx.x & 31;
    if (u >= N) return;

    const float* fp[5] = {f0, f1, f2, f3, f4};
    float2 f[5];
    #pragma unroll
    for (int k = 0; k < 5; k++)
        f[k] = ((const float2*)(fp[k] + (size_t)u * LATDIM))[lane];

    int d = 2 * lane;
    float p[5];
    #pragma unroll
    for (int j = 0; j < 5; j++) {
        float acc = 0.f;
        #pragma unroll
        for (int k = 0; k < 5; k++) {
            acc += f[k].x * sW[j * 320 + k * 64 + d];
            acc += f[k].y * sW[j * 320 + k * 64 + d + 1];
        }
        p[j] = acc;
    }
    #pragma unroll
    for (int j = 0; j < 5; j++)
        #pragma unroll
        for (int o = 16; o; o >>= 1)
            p[j] += __shfl_xor_sync(0xffffffffu, p[j], o);

    float mx = -1e30f;
    #pragma unroll
    for (int j = 0; j < 5; j++) {
        float l = p[j] + sb[j];
        l = l > 0.f ? l : 0.01f * l;
        p[j] = l;
        mx = fmaxf(mx, l);
    }
    float se = 0.f;
    #pragma unroll
    for (int j = 0; j < 5; j++) { p[j] = __expf(p[j] - mx); se += p[j]; }
    float inv = 1.f / se;

    float2 o2 = make_float2(0.f, 0.f);
    #pragma unroll
    for (int k = 0; k < 5; k++) {
        float w = p[k] * inv;
        o2.x += w * f[k].x;
        o2.y += w * f[k].y;
    }
    ((float2*)(out + (size_t)u * LATDIM))[lane] = o2;
}

// ---------------------------------------------------------------------------
// 5-way attention readout — item side: f0 fp32 (iE), f1..f4 fp16 shadows
// ---------------------------------------------------------------------------
__global__ void attn5h(const float* __restrict__ f0,
                       const __half* __restrict__ h1, const __half* __restrict__ h2,
                       const __half* __restrict__ h3, const __half* __restrict__ h4,
                       const float* __restrict__ W, const float* __restrict__ b,
                       float* __restrict__ out, int N)
{
    __shared__ float sW[5 * 320];
    __shared__ float sb[5];
    for (int i = threadIdx.x; i < 5 * 320; i += blockDim.x) sW[i] = W[i];
    if (threadIdx.x < 5) sb[threadIdx.x] = b[threadIdx.x];
    __syncthreads();

    int gt = blockIdx.x * blockDim.x + threadIdx.x;
    int u = gt >> 5;
    int lane = threadIdx.x & 31;
    if (u >= N) return;

    float2 f[5];
    f[0] = ((const float2*)(f0 + (size_t)u * LATDIM))[lane];
    const __half* hp[4] = {h1, h2, h3, h4};
    #pragma unroll
    for (int k = 0; k < 4; k++)
        f[k + 1] = __half22float2(((const __half2*)(hp[k] + (size_t)u * LATDIM))[lane]);

    int d = 2 * lane;
    float p[5];
    #pragma unroll
    for (int j = 0; j < 5; j++) {
        float acc = 0.f;
        #pragma unroll
        for (int k = 0; k < 5; k++) {
            acc += f[k].x * sW[j * 320 + k * 64 + d];
            acc += f[k].y * sW[j * 320 + k * 64 + d + 1];
        }
        p[j] = acc;
    }
    #pragma unroll
    for (int j = 0; j < 5; j++)
        #pragma unroll
        for (int o = 16; o; o >>= 1)
            p[j] += __shfl_xor_sync(0xffffffffu, p[j], o);

    float mx = -1e30f;
    #pragma unroll
    for (int j = 0; j < 5; j++) {
        float l = p[j] + sb[j];
        l = l > 0.f ? l : 0.01f * l;
        p[j] = l;
        mx = fmaxf(mx, l);
    }
    float se = 0.f;
    #pragma unroll
    for (int j = 0; j < 5; j++) { p[j] = __expf(p[j] - mx); se += p[j]; }
    float inv = 1.f / se;

    float2 o2 = make_float2(0.f, 0.f);
    #pragma unroll
    for (int k = 0; k < 5; k++) {
        float w = p[k] * inv;
        o2.x += w * f[k].x;
        o2.y += w * f[k].y;
    }
    ((float2*)(out + (size_t)u * LATDIM))[lane] = o2;
}

// ---------------------------------------------------------------------------

extern "C" void kernel_launch(void* const* d_in, const int* in_sizes, int n_in,
                              void* d_out, int out_size)
{
    const float* uE  = (const float*)d_in[0];
    const float* iE  = (const float*)d_in[1];
    const float* Wg  = (const float*)d_in[2];
    const float* bg  = (const float*)d_in[3];
    const float* WL1 = (const float*)d_in[4];
    const float* bL1 = (const float*)d_in[5];
    const float* WL2 = (const float*)d_in[6];
    const float* bL2 = (const float*)d_in[7];
    const int*   ir  = (const int*)d_in[8];
    const int*   ic  = (const int*)d_in[9];
    const float* iv  = (const float*)d_in[10];
    const int*   sr  = (const int*)d_in[11];
    const int*   sc  = (const int*)d_in[12];
    const float* sv  = (const float*)d_in[13];
    float* out = (float*)d_out;

    float *socB, *intU, *fuB;
    __half *combB, *socH, *it3;
    cudaGetSymbolAddress((void**)&socB,  g_soc);
    cudaGetSymbolAddress((void**)&intU,  g_interU);
    cudaGetSymbolAddress((void**)&fuB,   g_fusedU);
    cudaGetSymbolAddress((void**)&combB, g_comb);
    cudaGetSymbolAddress((void**)&socH,  g_soch);
    cudaGetSymbolAddress((void**)&it3,   g_it3);

    int *icnt, *icur, *iptr, *ibs, *scnt, *scur, *sptr, *sbs;
    int2 *icv, *scv;
    cudaGetSymbolAddress((void**)&icnt, g_icnt);
    cudaGetSymbolAddress((void**)&icur, g_icur);
    cudaGetSymbolAddress((void**)&iptr, g_iptr);
    cudaGetSymbolAddress((void**)&icv,  g_icv);
    cudaGetSymbolAddress((void**)&ibs,  g_ibsum);
    cudaGetSymbolAddress((void**)&scnt, g_scnt);
    cudaGetSymbolAddress((void**)&scur, g_scur);
    cudaGetSymbolAddress((void**)&sptr, g_sptr);
    cudaGetSymbolAddress((void**)&scv,  g_scv);
    cudaGetSymbolAddress((void**)&sbs,  g_sbsum);

    const size_t USZ = (size_t)N_USER * LATDIM;
    const size_t NSZ = (size_t)N_NODE * LATDIM;
    const int NB_I = (N_NODE + 2047) / 2048;   // 147
    const int NB_S = (N_USER + 2047) / 2048;   // 49
    const int nI2 = N_ITEM * LATDIM / 2;       // 6.4M half2

    const int GRID_U = (N_USER * 16 + 255) / 256;   // user-row spmm
    const int GRID_I = (N_ITEM * 16 + 255) / 256;   // item-row spmm

    // --- streams & events (s3 = item chain, highest priority) ---
    int prLow, prHigh;
    cudaDeviceGetStreamPriorityRange(&prLow, &prHigh);
    cudaStream_t s2, s3;
    cudaStreamCreateWithFlags(&s2, cudaStreamNonBlocking);
    cudaStreamCreateWithPriority(&s3, cudaStreamNonBlocking, prHigh);
    cudaEvent_t evFork, evSoc[4], evGate[4], evItem[4], evMain0, evAttnI;
    cudaEventCreateWithFlags(&evFork, cudaEventDisableTiming);
    cudaEventCreateWithFlags(&evMain0, cudaEventDisableTiming);
    cudaEventCreateWithFlags(&evAttnI, cudaEventDisableTiming);
    for (int k = 0; k < 4; k++) {
        cudaEventCreateWithFlags(&evSoc[k],  cudaEventDisableTiming);
        cudaEventCreateWithFlags(&evGate[k], cudaEventDisableTiming);
        cudaEventCreateWithFlags(&evItem[k], cudaEventDisableTiming);
    }

    cudaEventRecord(evFork, 0);
    cudaStreamWaitEvent(s2, evFork, 0);
    cudaStreamWaitEvent(s3, evFork, 0);

    // === s2: soc CSR build + soc chain (layers 1..4) ===
    hist_rows<<<(E_SOC + 255) / 256, 256, 0, s2>>>(sr, E_SOC, scnt);
    block_sum<<<NB_S, 256, 0, s2>>>(scnt, N_USER, sbs);
    scan_final<<<NB_S, 256, 0, s2>>>(scnt, N_USER, sbs, NB_S, sptr, scur, E_SOC);
    scatter_edges<<<(E_SOC + 255) / 256, 256, 0, s2>>>(sr, sc, sv, E_SOC, scur, scv);

    spmm_f32src<<<GRID_U, 256, 0, s2>>>(sptr, scv, uE, socB, socH, N_USER);
    cudaEventRecord(evSoc[0], s2);
    for (int k = 1; k < 4; k++) {
        spmm_f16<<<GRID_U, 256, 0, s2>>>(
            sptr, scv, socH + (size_t)(k - 1) * USZ,
            socB + (size_t)k * USZ,
            (k < 3) ? socH + (size_t)k * USZ : nullptr, 0, 0, N_USER);
        cudaEventRecord(evSoc[k], s2);
    }

    // === main: gate0 (needs only uE), then inter CSR build (+ iE fp16 conv) ===
    gate_fuse<<<(N_USER * 32 + 255) / 256, 256>>>(
        uE, uE, Wg, bg, fuB, combB);                       // comb[0] user region

    hist_rows<<<(E_INTER + 255) / 256, 256>>>(ir, E_INTER, icnt);
    block_sum<<<NB_I, 256>>>(icnt, N_NODE, ibs);
    scan_final<<<NB_I, 256>>>(icnt, N_NODE, ibs, NB_I, iptr, icur, E_INTER);
    {
        int tot = (E_INTER > nI2) ? E_INTER : nI2;
        scatter_conv<<<(tot + 255) / 256, 256>>>(ir, ic, iv, E_INTER, icur, icv,
                                                 (const float2*)iE,
                                                 (__half2*)(combB + USZ), nI2);
    }
    cudaEventRecord(evMain0, 0);   // comb[0] complete (gate0 + conv) & CSR ready

    // === layers 0..3: user-spmm on main, item-spmm on s3 ===
    for (int k = 0; k < 4; k++) {
        __half* combk = combB + (size_t)k * NSZ;

        // item rows -> comb[k+1] item region (k<3) or it3 (k=3); fp16 only
        cudaStreamWaitEvent(s3, (k == 0) ? evMain0 : evGate[k], 0);
        __half* dsth = (k < 3) ? combB + (size_t)(k + 1) * NSZ + USZ : it3;
        spmm_f16<<<GRID_I, 256, 0, s3>>>(
            iptr, icv, combk, nullptr, dsth, N_USER, N_USER, N_NODE);
        cudaEventRecord(evItem[k], s3);

        // user rows -> intU[k]; fp32 only (main)
        if (k >= 1) cudaStreamWaitEvent(0, evItem[k - 1], 0);
        spmm_f16<<<GRID_U, 256>>>(
            iptr, icv, combk, intU + (size_t)k * USZ, nullptr, 0, 0, N_USER);

        // gate_{k+1} on main (needs soc[k] + intU[k])
        cudaStreamWaitEvent(0, evSoc[k], 0);
        gate_fuse<<<(N_USER * 32 + 255) / 256, 256>>>(
            socB + (size_t)k * USZ, intU + (size_t)k * USZ,
            Wg + (k + 1) * 256, bg + (k + 1) * 2,
            fuB + (size_t)(k + 1) * USZ,
            (k < 3) ? combB + (size_t)(k + 1) * NSZ : nullptr);
        if (k < 3) cudaEventRecord(evGate[k + 1], 0);
    }

    // --- attention readouts: item side on s3 (deps already there), user on main ---
    attn5h<<<(N_ITEM * 32 + 255) / 256, 256, 0, s3>>>(
        iE,
        combB + 1 * NSZ + USZ, combB + 2 * NSZ + USZ, combB + 3 * NSZ + USZ, it3,
        WL2, bL2, out + USZ, N_ITEM);
    cudaEventRecord(evAttnI, s3);

    attn5<<<(N_USER * 32 + 255) / 256, 256>>>(
        fuB, fuB + USZ, fuB + 2 * USZ, fuB + 3 * USZ, fuB + 4 * USZ,
        WL1, bL1, out, N_USER);

    // join s3 back into main (capture fork must be closed on the origin stream)
    cudaStreamWaitEvent(0, evAttnI, 0);

    // --- cleanup ---
    cudaEventDestroy(evFork);
    cudaEventDestroy(evMain0);
    cudaEventDestroy(evAttnI);
    for (int k = 0; k < 4; k++) {
        cudaEventDestroy(evSoc[k]);
        cudaEventDestroy(evGate[k]);
        cudaEventDestroy(evItem[k]);
    }
    cudaStreamDestroy(s2);
    cudaStreamDestroy(s3);
}

// round 16
// speedup vs baseline: 1.2306x; 1.0458x over previous
#include <cuda_runtime.h>
#include <cuda_fp16.h>

#define N_USER 100000
#define N_ITEM 200000
#define N_NODE 300000
#define LATDIM 64
#define E_INTER 4000000
#define E_SOC   2000000

// All dense intermediates are fp16 now.
// comb[k] = [ fp16(gate_k user rows) ; fp16(inter_{k} item rows) ]
__device__ __align__(256) __half g_comb [4][(size_t)N_NODE * LATDIM];
__device__ __align__(256) __half g_soch [4][(size_t)N_USER * LATDIM];  // soc layers 1..4
__device__ __align__(256) __half g_intUh[4][(size_t)N_USER * LATDIM];  // inter user rows
__device__ __align__(256) __half g_fuh  [5][(size_t)N_USER * LATDIM];  // fused user vectors
__device__ __align__(256) __half g_it3  [(size_t)N_ITEM * LATDIM];     // item rows of inter spmm 3

// CSR scratch. cnt arrays self-reset (zeroed by scan_final after use).
__device__ int  g_icnt[N_NODE];
__device__ int  g_icur[N_NODE];
__device__ int  g_iptr[N_NODE + 1];
__device__ __align__(16) int2 g_icv[E_INTER];
__device__ int  g_ibsum[256];

__device__ int  g_scnt[N_USER];
__device__ int  g_scur[N_USER];
__device__ int  g_sptr[N_USER + 1];
__device__ __align__(16) int2 g_scv[E_SOC];
__device__ int  g_sbsum[256];

// ---------------------------------------------------------------------------
// CSR build
// ---------------------------------------------------------------------------
__global__ void hist_rows(const int* __restrict__ rows, int E, int* __restrict__ cnt)
{
    int i = blockIdx.x * blockDim.x + threadIdx.x;
    if (i < E) atomicAdd(&cnt[rows[i]], 1);
}

__global__ void block_sum(const int* __restrict__ cnt, int N, int* __restrict__ bsum)
{
    __shared__ int sh[256];
    int base = blockIdx.x * 2048;
    int s = 0;
    for (int i = threadIdx.x; i < 2048; i += 256) {
        int idx = base + i;
        s += (idx < N) ? cnt[idx] : 0;
    }
    sh[threadIdx.x] = s;
    __syncthreads();
    for (int o = 128; o; o >>= 1) {
        if (threadIdx.x < o) sh[threadIdx.x] += sh[threadIdx.x + o];
        __syncthreads();
    }
    if (threadIdx.x == 0) bsum[blockIdx.x] = sh[0];
}

__global__ void scan_final(int* __restrict__ cnt, int N,
                           const int* __restrict__ bsum, int NB,
                           int* __restrict__ ptr, int* __restrict__ cur, int E)
{
    __shared__ int shb[256];
    __shared__ int sh[256];
    int t = threadIdx.x;

    shb[t] = (t < NB) ? bsum[t] : 0;
    __syncthreads();
    for (int o = 1; o < 256; o <<= 1) {
        int y = (t >= o) ? shb[t - o] : 0;
        __syncthreads();
        shb[t] += y;
        __syncthreads();
    }
    int block_off = (blockIdx.x == 0) ? 0 : shb[blockIdx.x - 1];

    int base = blockIdx.x * 2048 + t * 8;
    int loc[8];
    int s = 0;
    #pragma unroll
    for (int j = 0; j < 8; j++) {
        int idx = base + j;
        loc[j] = (idx < N) ? cnt[idx] : 0;
        if (idx < N) cnt[idx] = 0;           // self-reset for next call
        s += loc[j];
    }
    sh[t] = s;
    __syncthreads();
    for (int o = 1; o < 256; o <<= 1) {
        int y = (t >= o) ? sh[t - o] : 0;
        __syncthreads();
        sh[t] += y;
        __syncthreads();
    }
    int run = block_off + sh[t] - s;
    #pragma unroll
    for (int j = 0; j < 8; j++) {
        int idx = base + j;
        if (idx < N) { ptr[idx] = run; cur[idx] = run; run += loc[j]; }
    }
    if (blockIdx.x == 0 && t == 0) ptr[N] = E;
}

__global__ void scatter_edges(const int* __restrict__ rows, const int* __restrict__ cols,
                              const float* __restrict__ vals, int E,
                              int* __restrict__ cur, int2* __restrict__ cv)
{
    int i = blockIdx.x * blockDim.x + threadIdx.x;
    if (i >= E) return;
    int p = atomicAdd(&cur[rows[i]], 1);
    cv[p] = make_int2(cols[i], __float_as_int(vals[i]));
}

__global__ void scatter_conv(const int* __restrict__ rows, const int* __restrict__ cols,
                             const float* __restrict__ vals, int E,
                             int* __restrict__ cur, int2* __restrict__ cv,
                             const float2* __restrict__ iE2, __half2* __restrict__ dst2,
                             int nI2)
{
    int i = blockIdx.x * blockDim.x + threadIdx.x;
    if (i < E) {
        int p = atomicAdd(&cur[rows[i]], 1);
        cv[p] = make_int2(cols[i], __float_as_int(vals[i]));
    }
    if (i < nI2) dst2[i] = __float22half2_rn(iE2[i]);
}

// ---------------------------------------------------------------------------
// CSR SpMM: 16 lanes/row, pair-lane split; row range [r0, r1).
//   fp32 accumulate; SINGLE fp16 store per row (pair 1) at dsth[row - hoff].
//   Tail ladder 8 -> 4 -> 2 -> 1.
// ---------------------------------------------------------------------------
__device__ __forceinline__ void acc8(float* acc, uint4 w, float v)
{
    float2 f0 = __half22float2(*reinterpret_cast<__half2*>(&w.x));
    float2 f1 = __half22float2(*reinterpret_cast<__half2*>(&w.y));
    float2 f2 = __half22float2(*reinterpret_cast<__half2*>(&w.z));
    float2 f3 = __half22float2(*reinterpret_cast<__half2*>(&w.w));
    acc[0] += v * f0.x; acc[1] += v * f0.y;
    acc[2] += v * f1.x; acc[3] += v * f1.y;
    acc[4] += v * f2.x; acc[5] += v * f2.y;
    acc[6] += v * f3.x; acc[7] += v * f3.y;
}

__device__ __forceinline__ void store_h(const float* acc, __half* dsth,
                                        size_t rowoff, int q)
{
    __half2 h0 = __floats2half2_rn(acc[0], acc[1]);
    __half2 h1 = __floats2half2_rn(acc[2], acc[3]);
    __half2 h2 = __floats2half2_rn(acc[4], acc[5]);
    __half2 h3 = __floats2half2_rn(acc[6], acc[7]);
    uint4 pk;
    pk.x = *reinterpret_cast<unsigned*>(&h0);
    pk.y = *reinterpret_cast<unsigned*>(&h1);
    pk.z = *reinterpret_cast<unsigned*>(&h2);
    pk.w = *reinterpret_cast<unsigned*>(&h3);
    ((uint4*)(dsth + rowoff * LATDIM))[q] = pk;
}

__global__ void __launch_bounds__(256) spmm_f16(
    const int* __restrict__ ptr, const int2* __restrict__ cv,
    const __half* __restrict__ src,
    __half* __restrict__ dsth, int hoff, int r0, int r1)
{
    int t = blockIdx.x * blockDim.x + threadIdx.x;
    int row = r0 + (t >> 4);
    int lane = threadIdx.x & 15;
    int pair = lane >> 3;
    int q    = lane & 7;
    bool valid = row < r1;

    int s = 0, e = 0;
    if (valid) { s = __ldg(ptr + row); e = __ldg(ptr + row + 1); }

    float acc[8] = {0.f, 0.f, 0.f, 0.f, 0.f, 0.f, 0.f, 0.f};
    int i = s;
    for (; i + 8 <= e; i += 8) {
        int2 a0 = __ldg(cv + i     + pair);
        int2 a1 = __ldg(cv + i + 2 + pair);
        int2 a2 = __ldg(cv + i + 4 + pair);
        int2 a3 = __ldg(cv + i + 6 + pair);
        uint4 w0 = __ldg((const uint4*)(src + (size_t)a0.x * LATDIM) + q);
        uint4 w1 = __ldg((const uint4*)(src + (size_t)a1.x * LATDIM) + q);
        uint4 w2 = __ldg((const uint4*)(src + (size_t)a2.x * LATDIM) + q);
        uint4 w3 = __ldg((const uint4*)(src + (size_t)a3.x * LATDIM) + q);
        acc8(acc, w0, __int_as_float(a0.y));
        acc8(acc, w1, __int_as_float(a1.y));
        acc8(acc, w2, __int_as_float(a2.y));
        acc8(acc, w3, __int_as_float(a3.y));
    }
    if (i + 4 <= e) {
        int2 a0 = __ldg(cv + i     + pair);
        int2 a1 = __ldg(cv + i + 2 + pair);
        uint4 w0 = __ldg((const uint4*)(src + (size_t)a0.x * LATDIM) + q);
        uint4 w1 = __ldg((const uint4*)(src + (size_t)a1.x * LATDIM) + q);
        acc8(acc, w0, __int_as_float(a0.y));
        acc8(acc, w1, __int_as_float(a1.y));
        i += 4;
    }
    if (i + 2 <= e) {
        int2 a = __ldg(cv + i + pair);
        uint4 w = __ldg((const uint4*)(src + (size_t)a.x * LATDIM) + q);
        acc8(acc, w, __int_as_float(a.y));
        i += 2;
    }
    if (i < e && pair == 0) {
        int2 a = __ldg(cv + i);
        uint4 w = __ldg((const uint4*)(src + (size_t)a.x * LATDIM) + q);
        acc8(acc, w, __int_as_float(a.y));
    }

    #pragma unroll
    for (int j = 0; j < 8; j++)
        acc[j] += __shfl_xor_sync(0xffffffffu, acc[j], 8);

    if (valid && pair == 1)
        store_h(acc, dsth, (size_t)(row - hoff), q);
}

// fp32-source variant (soc layer 0 only, gathering uE); fp16 out only
__global__ void __launch_bounds__(256) spmm_f32src(
    const int* __restrict__ ptr, const int2* __restrict__ cv,
    const float* __restrict__ src,
    __half* __restrict__ dsth, int nrows)
{
    int hw = (blockIdx.x * blockDim.x + threadIdx.x) >> 4;
    int q  = threadIdx.x & 15;
    if (hw >= nrows) return;
    int s = __ldg(ptr + hw);
    int e = __ldg(ptr + hw + 1);
    float4 acc = make_float4(0.f, 0.f, 0.f, 0.f);
    int i = s;
    for (; i + 4 <= e; i += 4) {
        int2 a0 = __ldg(cv + i),     a1 = __ldg(cv + i + 1);
        int2 a2 = __ldg(cv + i + 2), a3 = __ldg(cv + i + 3);
        float4 x0 = __ldg((const float4*)(src + (size_t)a0.x * LATDIM) + q);
        float4 x1 = __ldg((const float4*)(src + (size_t)a1.x * LATDIM) + q);
        float4 x2 = __ldg((const float4*)(src + (size_t)a2.x * LATDIM) + q);
        float4 x3 = __ldg((const float4*)(src + (size_t)a3.x * LATDIM) + q);
        float v0 = __int_as_float(a0.y), v1 = __int_as_float(a1.y);
        float v2 = __int_as_float(a2.y), v3 = __int_as_float(a3.y);
        acc.x += v0 * x0.x; acc.y += v0 * x0.y; acc.z += v0 * x0.z; acc.w += v0 * x0.w;
        acc.x += v1 * x1.x; acc.y += v1 * x1.y; acc.z += v1 * x1.z; acc.w += v1 * x1.w;
        acc.x += v2 * x2.x; acc.y += v2 * x2.y; acc.z += v2 * x2.z; acc.w += v2 * x2.w;
        acc.x += v3 * x3.x; acc.y += v3 * x3.y; acc.z += v3 * x3.z; acc.w += v3 * x3.w;
    }
    if (i + 2 <= e) {
        int2 a0 = __ldg(cv + i), a1 = __ldg(cv + i + 1);
        float4 x0 = __ldg((const float4*)(src + (size_t)a0.x * LATDIM) + q);
        float4 x1 = __ldg((const float4*)(src + (size_t)a1.x * LATDIM) + q);
        float v0 = __int_as_float(a0.y), v1 = __int_as_float(a1.y);
        acc.x += v0 * x0.x; acc.y += v0 * x0.y; acc.z += v0 * x0.z; acc.w += v0 * x0.w;
        acc.x += v1 * x1.x; acc.y += v1 * x1.y; acc.z += v1 * x1.z; acc.w += v1 * x1.w;
        i += 2;
    }
    if (i < e) {
        int2 a = __ldg(cv + i);
        float4 x = __ldg((const float4*)(src + (size_t)a.x * LATDIM) + q);
        float v = __int_as_float(a.y);
        acc.x += v * x.x; acc.y += v * x.y; acc.z += v * x.z; acc.w += v * x.w;
    }
    __half2 h0 = __floats2half2_rn(acc.x, acc.y);
    __half2 h1 = __floats2half2_rn(acc.z, acc.w);
    uint2 pk;
    pk.x = *reinterpret_cast<unsigned*>(&h0);
    pk.y = *reinterpret_cast<unsigned*>(&h1);
    ((uint2*)(dsth + (size_t)hw * LATDIM))[q] = pk;
}

// ---------------------------------------------------------------------------
// Gates: fp32 math; fp16 outputs (comb user region + fused buffer).
// f32-input variant (layer 0, reads uE) and f16-input variant (layers 1..4).
// ---------------------------------------------------------------------------
__device__ __forceinline__ void gate_core(float2 za, float2 ha,
                                          const float* __restrict__ Wg,
                                          const float* __restrict__ bg,
                                          int lane, float2& o2)
{
    int d = 2 * lane;
    float p0 = za.x * Wg[d]       + za.y * Wg[d + 1]
             + ha.x * Wg[64 + d]  + ha.y * Wg[64 + d + 1];
    float p1 = za.x * Wg[128 + d]      + za.y * Wg[128 + d + 1]
             + ha.x * Wg[128 + 64 + d] + ha.y * Wg[128 + 64 + d + 1];
    #pragma unroll
    for (int o = 16; o; o >>= 1) {
        p0 += __shfl_xor_sync(0xffffffffu, p0, o);
        p1 += __shfl_xor_sync(0xffffffffu, p1, o);
    }
    float l0 = p0 + bg[0];
    float l1 = p1 + bg[1];
    l0 = l0 > 0.f ? l0 : 0.01f * l0;
    l1 = l1 > 0.f ? l1 : 0.01f * l1;
    float mx = fmaxf(l0, l1);
    float e0 = __expf(l0 - mx), e1 = __expf(l1 - mx);
    float inv = 1.f / (e0 + e1);
    float m0 = e0 * inv, m1 = e1 * inv;
    o2 = make_float2(za.x * m0 + ha.x * m1, za.y * m0 + ha.y * m1);
}

__global__ void gate_fuse_f32(const float* __restrict__ uu, const float* __restrict__ hi,
                              const float* __restrict__ Wg, const float* __restrict__ bg,
                              __half* __restrict__ outh1, __half* __restrict__ outh2)
{
    int gt = blockIdx.x * blockDim.x + threadIdx.x;
    int u = gt >> 5;
    int lane = threadIdx.x & 31;
    if (u >= N_USER) return;
    float2 za = ((const float2*)(uu + (size_t)u * LATDIM))[lane];
    float2 ha = ((const float2*)(hi + (size_t)u * LATDIM))[lane];
    float2 o2;
    gate_core(za, ha, Wg, bg, lane, o2);
    __half2 oh = __float22half2_rn(o2);
    ((__half2*)(outh1 + (size_t)u * LATDIM))[lane] = oh;
    if (outh2 != nullptr)
        ((__half2*)(outh2 + (size_t)u * LATDIM))[lane] = oh;
}

__global__ void gate_fuse_f16(const __half* __restrict__ uu, const __half* __restrict__ hi,
                              const float* __restrict__ Wg, const float* __restrict__ bg,
                              __half* __restrict__ outh1, __half* __restrict__ outh2)
{
    int gt = blockIdx.x * blockDim.x + threadIdx.x;
    int u = gt >> 5;
    int lane = threadIdx.x & 31;
    if (u >= N_USER) return;
    float2 za = __half22float2(((const __half2*)(uu + (size_t)u * LATDIM))[lane]);
    float2 ha = __half22float2(((const __half2*)(hi + (size_t)u * LATDIM))[lane]);
    float2 o2;
    gate_core(za, ha, Wg, bg, lane, o2);
    __half2 oh = __float22half2_rn(o2);
    ((__half2*)(outh1 + (size_t)u * LATDIM))[lane] = oh;
    if (outh2 != nullptr)
        ((__half2*)(outh2 + (size_t)u * LATDIM))[lane] = oh;
}

// ---------------------------------------------------------------------------
// 5-way attention readouts. User side: all five fp16. Item side: f0 fp32 (iE),
// f1..f4 fp16 shadows. Both compute fp32, write fp32 output.
// ---------------------------------------------------------------------------
__device__ __forceinline__ void attn_core(float2* f, const float* sW, const float* sb,
                                          int lane, float2& o2)
{
    int d = 2 * lane;
    float p[5];
    #pragma unroll
    for (int j = 0; j < 5; j++) {
        float acc = 0.f;
        #pragma unroll
        for (int k = 0; k < 5; k++) {
            acc += f[k].x * sW[j * 320 + k * 64 + d];
            acc += f[k].y * sW[j * 320 + k * 64 + d + 1];
        }
        p[j] = acc;
    }
    #pragma unroll
    for (int j = 0; j < 5; j++)
        #pragma unroll
        for (int o = 16; o; o >>= 1)
            p[j] += __shfl_xor_sync(0xffffffffu, p[j], o);

    float mx = -1e30f;
    #pragma unroll
    for (int j = 0; j < 5; j++) {
        float l = p[j] + sb[j];
        l = l > 0.f ? l : 0.01f * l;
        p[j] = l;
        mx = fmaxf(mx, l);
    }
    float se = 0.f;
    #pragma unroll
    for (int j = 0; j < 5; j++) { p[j] = __expf(p[j] - mx); se += p[j]; }
    float inv = 1.f / se;

    o2 = make_float2(0.f, 0.f);
    #pragma unroll
    for (int k = 0; k < 5; k++) {
        float w = p[k] * inv;
        o2.x += w * f[k].x;
        o2.y += w * f[k].y;
    }
}

__global__ void attn5_allh(const __half* __restrict__ h0, const __half* __restrict__ h1,
                           const __half* __restrict__ h2, const __half* __restrict__ h3,
                           const __half* __restrict__ h4,
                           const float* __restrict__ W, const float* __restrict__ b,
                           float* __restrict__ out, int N)
{
    __shared__ float sW[5 * 320];
    __shared__ float sb[5];
    for (int i = threadIdx.x; i < 5 * 320; i += blockDim.x) sW[i] = W[i];
    if (threadIdx.x < 5) sb[threadIdx.x] = b[threadIdx.x];
    __syncthreads();

    int gt = blockIdx.x * blockDim.x + threadIdx.x;
    int u = gt >> 5;
    int lane = threadIdx.x & 31;
    if (u >= N) return;

    const __half* hp[5] = {h0, h1, h2, h3, h4};
    float2 f[5];
    #pragma unroll
    for (int k = 0; k < 5; k++)
        f[k] = __half22float2(((const __half2*)(hp[k] + (size_t)u * LATDIM))[lane]);

    float2 o2;
    attn_core(f, sW, sb, lane, o2);
    ((float2*)(out + (size_t)u * LATDIM))[lane] = o2;
}

__global__ void attn5h(const float* __restrict__ f0,
                       const __half* __restrict__ h1, const __half* __restrict__ h2,
                       const __half* __restrict__ h3, const __half* __restrict__ h4,
                       const float* __restrict__ W, const float* __restrict__ b,
                       float* __restrict__ out, int N)
{
    __shared__ float sW[5 * 320];
    __shared__ float sb[5];
    for (int i = threadIdx.x; i < 5 * 320; i += blockDim.x) sW[i] = W[i];
    if (threadIdx.x < 5) sb[threadIdx.x] = b[threadIdx.x];
    __syncthreads();

    int gt = blockIdx.x * blockDim.x + threadIdx.x;
    int u = gt >> 5;
    int lane = threadIdx.x & 31;
    if (u >= N) return;

    float2 f[5];
    f[0] = ((const float2*)(f0 + (size_t)u * LATDIM))[lane];
    const __half* hp[4] = {h1, h2, h3, h4};
    #pragma unroll
    for (int k = 0; k < 4; k++)
        f[k + 1] = __half22float2(((const __half2*)(hp[k] + (size_t)u * LATDIM))[lane]);

    float2 o2;
    attn_core(f, sW, sb, lane, o2);
    ((float2*)(out + (size_t)u * LATDIM))[lane] = o2;
}

// ---------------------------------------------------------------------------

extern "C" void kernel_launch(void* const* d_in, const int* in_sizes, int n_in,
                              void* d_out, int out_size)
{
    const float* uE  = (const float*)d_in[0];
    const float* iE  = (const float*)d_in[1];
    const float* Wg  = (const float*)d_in[2];
    const float* bg  = (const float*)d_in[3];
    const float* WL1 = (const float*)d_in[4];
    const float* bL1 = (const float*)d_in[5];
    const float* WL2 = (const float*)d_in[6];
    const float* bL2 = (const float*)d_in[7];
    const int*   ir  = (const int*)d_in[8];
    const int*   ic  = (const int*)d_in[9];
    const float* iv  = (const float*)d_in[10];
    const int*   sr  = (const int*)d_in[11];
    const int*   sc  = (const int*)d_in[12];
    const float* sv  = (const float*)d_in[13];
    float* out = (float*)d_out;

    __half *combB, *socH, *intUh, *fuH, *it3;
    cudaGetSymbolAddress((void**)&combB, g_comb);
    cudaGetSymbolAddress((void**)&socH,  g_soch);
    cudaGetSymbolAddress((void**)&intUh, g_intUh);
    cudaGetSymbolAddress((void**)&fuH,   g_fuh);
    cudaGetSymbolAddress((void**)&it3,   g_it3);

    int *icnt, *icur, *iptr, *ibs, *scnt, *scur, *sptr, *sbs;
    int2 *icv, *scv;
    cudaGetSymbolAddress((void**)&icnt, g_icnt);
    cudaGetSymbolAddress((void**)&icur, g_icur);
    cudaGetSymbolAddress((void**)&iptr, g_iptr);
    cudaGetSymbolAddress((void**)&icv,  g_icv);
    cudaGetSymbolAddress((void**)&ibs,  g_ibsum);
    cudaGetSymbolAddress((void**)&scnt, g_scnt);
    cudaGetSymbolAddress((void**)&scur, g_scur);
    cudaGetSymbolAddress((void**)&sptr, g_sptr);
    cudaGetSymbolAddress((void**)&scv,  g_scv);
    cudaGetSymbolAddress((void**)&sbs,  g_sbsum);

    const size_t USZ = (size_t)N_USER * LATDIM;
    const size_t NSZ = (size_t)N_NODE * LATDIM;
    const int NB_I = (N_NODE + 2047) / 2048;   // 147
    const int NB_S = (N_USER + 2047) / 2048;   // 49
    const int nI2 = N_ITEM * LATDIM / 2;       // 6.4M half2

    const int GRID_U = (N_USER * 16 + 255) / 256;
    const int GRID_I = (N_ITEM * 16 + 255) / 256;

    // --- streams & events (s3 = item chain, highest priority) ---
    int prLow, prHigh;
    cudaDeviceGetStreamPriorityRange(&prLow, &prHigh);
    cudaStream_t s2, s3;
    cudaStreamCreateWithFlags(&s2, cudaStreamNonBlocking);
    cudaStreamCreateWithPriority(&s3, cudaStreamNonBlocking, prHigh);
    cudaEvent_t evFork, evSoc[4], evGate[4], evItem[4], evMain0, evAttnI;
    cudaEventCreateWithFlags(&evFork, cudaEventDisableTiming);
    cudaEventCreateWithFlags(&evMain0, cudaEventDisableTiming);
    cudaEventCreateWithFlags(&evAttnI, cudaEventDisableTiming);
    for (int k = 0; k < 4; k++) {
        cudaEventCreateWithFlags(&evSoc[k],  cudaEventDisableTiming);
        cudaEventCreateWithFlags(&evGate[k], cudaEventDisableTiming);
        cudaEventCreateWithFlags(&evItem[k], cudaEventDisableTiming);
    }

    cudaEventRecord(evFork, 0);
    cudaStreamWaitEvent(s2, evFork, 0);
    cudaStreamWaitEvent(s3, evFork, 0);

    // === s2: soc CSR build + soc chain (layers 1..4), all fp16 outputs ===
    hist_rows<<<(E_SOC + 255) / 256, 256, 0, s2>>>(sr, E_SOC, scnt);
    block_sum<<<NB_S, 256, 0, s2>>>(scnt, N_USER, sbs);
    scan_final<<<NB_S, 256, 0, s2>>>(scnt, N_USER, sbs, NB_S, sptr, scur, E_SOC);
    scatter_edges<<<(E_SOC + 255) / 256, 256, 0, s2>>>(sr, sc, sv, E_SOC, scur, scv);

    spmm_f32src<<<GRID_U, 256, 0, s2>>>(sptr, scv, uE, socH, N_USER);
    cudaEventRecord(evSoc[0], s2);
    for (int k = 1; k < 4; k++) {
        spmm_f16<<<GRID_U, 256, 0, s2>>>(
            sptr, scv, socH + (size_t)(k - 1) * USZ,
            socH + (size_t)k * USZ, 0, 0, N_USER);
        cudaEventRecord(evSoc[k], s2);
    }

    // === main: gate0 (uE only), then inter CSR build (+ iE fp16 conv) ===
    gate_fuse_f32<<<(N_USER * 32 + 255) / 256, 256>>>(
        uE, uE, Wg, bg, combB, fuH);                   // comb[0] user + fused[0]

    hist_rows<<<(E_INTER + 255) / 256, 256>>>(ir, E_INTER, icnt);
    block_sum<<<NB_I, 256>>>(icnt, N_NODE, ibs);
    scan_final<<<NB_I, 256>>>(icnt, N_NODE, ibs, NB_I, iptr, icur, E_INTER);
    {
        int tot = (E_INTER > nI2) ? E_INTER : nI2;
        scatter_conv<<<(tot + 255) / 256, 256>>>(ir, ic, iv, E_INTER, icur, icv,
                                                 (const float2*)iE,
                                                 (__half2*)(combB + USZ), nI2);
    }
    cudaEventRecord(evMain0, 0);   // comb[0] complete & inter CSR ready

    // === layers 0..3: user-spmm on main, item-spmm on s3 ===
    for (int k = 0; k < 4; k++) {
        __half* combk = combB + (size_t)k * NSZ;

        // item rows -> comb[k+1] item region (k<3) or it3 (k=3)
        cudaStreamWaitEvent(s3, (k == 0) ? evMain0 : evGate[k], 0);
        __half* dsthI = (k < 3) ? combB + (size_t)(k + 1) * NSZ + USZ : it3;
        spmm_f16<<<GRID_I, 256, 0, s3>>>(
            iptr, icv, combk, dsthI, N_USER, N_USER, N_NODE);
        cudaEventRecord(evItem[k], s3);

        // user rows -> intUh[k] (main)
        if (k >= 1) cudaStreamWaitEvent(0, evItem[k - 1], 0);
        spmm_f16<<<GRID_U, 256>>>(
            iptr, icv, combk, intUh + (size_t)k * USZ, 0, 0, N_USER);

        // gate_{k+1}: socH[k] + intUh[k] -> comb[k+1] user (k<3) + fused[k+1]
        cudaStreamWaitEvent(0, evSoc[k], 0);
        gate_fuse_f16<<<(N_USER * 32 + 255) / 256, 256>>>(
            socH + (size_t)k * USZ, intUh + (size_t)k * USZ,
            Wg + (k + 1) * 256, bg + (k + 1) * 2,
            fuH + (size_t)(k + 1) * USZ,
            (k < 3) ? combB + (size_t)(k + 1) * NSZ : nullptr);
        if (k < 3) cudaEventRecord(evGate[k + 1], 0);
    }

    // --- attention readouts: item side on s3, user on main ---
    attn5h<<<(N_ITEM * 32 + 255) / 256, 256, 0, s3>>>(
        iE,
        combB + 1 * NSZ + USZ, combB + 2 * NSZ + USZ, combB + 3 * NSZ + USZ, it3,
        WL2, bL2, out + USZ, N_ITEM);
    cudaEventRecord(evAttnI, s3);

    attn5_allh<<<(N_USER * 32 + 255) / 256, 256>>>(
        fuH, fuH + USZ, fuH + 2 * USZ, fuH + 3 * USZ, fuH + 4 * USZ,
        WL1, bL1, out, N_USER);

    // join s3 back into main
    cudaStreamWaitEvent(0, evAttnI, 0);

    // --- cleanup ---
    cudaEventDestroy(evFork);
    cudaEventDestroy(evMain0);
    cudaEventDestroy(evAttnI);
    for (int k = 0; k < 4; k++) {
        cudaEventDestroy(evSoc[k]);
        cudaEventDestroy(evGate[k]);
        cudaEventDestroy(evItem[k]);
    }
    cudaStreamDestroy(s2);
    cudaStreamDestroy(s3);
}